// round 1
// baseline (speedup 1.0000x reference)
#include <cuda_runtime.h>
#include <cuda_bf16.h>
#include <math.h>

// ---------------------------------------------------------------------------
// Problem constants
// ---------------------------------------------------------------------------
#define S_LEN     8192
#define T_LEN     256
#define NUM_HEADS 16
#define HEAD_DIM  64
#define INNER     1024          // NUM_HEADS * HEAD_DIM
#define SPARSE_N  8
#define G_LEN     (S_LEN / SPARSE_N)        // 1024
#define STOT      (G_LEN + T_LEN)           // 1280
#define NJH       (SPARSE_N * NUM_HEADS)    // 128 (batch*head pairs)
#define EPS_RMS   1e-5f
#define ATTN_SCALE 0.125f       // 1/sqrt(64)

// ---------------------------------------------------------------------------
// Static device scratch (no allocation allowed in kernel_launch)
// ---------------------------------------------------------------------------
__device__ float g_qraw[S_LEN * INNER];
__device__ float g_kraw[S_LEN * INNER];
__device__ float g_vraw[S_LEN * INNER];
__device__ float g_aqraw[T_LEN * INNER];
__device__ float g_akraw[T_LEN * INNER];
__device__ float g_avraw[T_LEN * INNER];
// attention layout: [j*16+h][seq (0..1279)][64]
__device__ float g_QA[NJH * STOT * HEAD_DIM];
__device__ float g_KA[NJH * STOT * HEAD_DIM];
__device__ float g_VA[NJH * STOT * HEAD_DIM];
__device__ float g_OA[NJH * STOT * HEAD_DIM];
__device__ float g_vis[S_LEN * INNER];
__device__ float g_txt[T_LEN * INNER];

// ---------------------------------------------------------------------------
// SGEMM (NT):  C[m][n] = sum_k A[m][k] * W[n][k]  (+ bias[n])
// A: [M][K] row-major, W: [N][K] row-major, C: [M][N] row-major
// BM=BN=128, BK=8, 256 threads, 8x8 per-thread micro-tile
// Requires M%128==0, N%128==0, K%8==0 (true for all calls here).
// ---------------------------------------------------------------------------
#define GBM 128
#define GBN 128
#define GBK 8

__global__ void __launch_bounds__(256)
sgemm_nt_kernel(const float* __restrict__ A, const float* __restrict__ W,
                const float* __restrict__ bias, float* __restrict__ C,
                int M, int N, int K)
{
    __shared__ float As[GBK][GBM];
    __shared__ float Ws[GBK][GBN];

    const int t  = threadIdx.x;
    const int m0 = blockIdx.y * GBM;
    const int n0 = blockIdx.x * GBN;
    const int ty = t >> 4;       // 0..15
    const int tx = t & 15;       // 0..15

    const int lrow = t >> 1;         // 0..127
    const int lcol = (t & 1) * 4;    // 0 or 4

    float acc[8][8];
#pragma unroll
    for (int i = 0; i < 8; i++)
#pragma unroll
        for (int j = 0; j < 8; j++) acc[i][j] = 0.f;

    const float* Ap = A + (size_t)(m0 + lrow) * K + lcol;
    const float* Wp = W + (size_t)(n0 + lrow) * K + lcol;

    for (int k0 = 0; k0 < K; k0 += GBK) {
        float4 av = *(const float4*)(Ap + k0);
        float4 wv = *(const float4*)(Wp + k0);
        As[lcol + 0][lrow] = av.x;
        As[lcol + 1][lrow] = av.y;
        As[lcol + 2][lrow] = av.z;
        As[lcol + 3][lrow] = av.w;
        Ws[lcol + 0][lrow] = wv.x;
        Ws[lcol + 1][lrow] = wv.y;
        Ws[lcol + 2][lrow] = wv.z;
        Ws[lcol + 3][lrow] = wv.w;
        __syncthreads();

#pragma unroll
        for (int kk = 0; kk < GBK; kk++) {
            float a[8], b[8];
            float4 a0 = *(const float4*)(&As[kk][ty * 8 + 0]);
            float4 a1 = *(const float4*)(&As[kk][ty * 8 + 4]);
            float4 b0 = *(const float4*)(&Ws[kk][tx * 8 + 0]);
            float4 b1 = *(const float4*)(&Ws[kk][tx * 8 + 4]);
            a[0]=a0.x; a[1]=a0.y; a[2]=a0.z; a[3]=a0.w;
            a[4]=a1.x; a[5]=a1.y; a[6]=a1.z; a[7]=a1.w;
            b[0]=b0.x; b[1]=b0.y; b[2]=b0.z; b[3]=b0.w;
            b[4]=b1.x; b[5]=b1.y; b[6]=b1.z; b[7]=b1.w;
#pragma unroll
            for (int i = 0; i < 8; i++)
#pragma unroll
                for (int j = 0; j < 8; j++)
                    acc[i][j] += a[i] * b[j];
        }
        __syncthreads();
    }

#pragma unroll
    for (int i = 0; i < 8; i++) {
        const int m = m0 + ty * 8 + i;
        float* Cp = C + (size_t)m * N + n0 + tx * 8;
        float4 c0, c1;
        if (bias) {
            const float* bp = bias + n0 + tx * 8;
            c0 = make_float4(acc[i][0] + bp[0], acc[i][1] + bp[1],
                             acc[i][2] + bp[2], acc[i][3] + bp[3]);
            c1 = make_float4(acc[i][4] + bp[4], acc[i][5] + bp[5],
                             acc[i][6] + bp[6], acc[i][7] + bp[7]);
        } else {
            c0 = make_float4(acc[i][0], acc[i][1], acc[i][2], acc[i][3]);
            c1 = make_float4(acc[i][4], acc[i][5], acc[i][6], acc[i][7]);
        }
        *(float4*)(Cp + 0) = c0;
        *(float4*)(Cp + 4) = c1;
    }
}

// ---------------------------------------------------------------------------
// Warp reduction helper
// ---------------------------------------------------------------------------
__device__ __forceinline__ float warp_sum32(float v) {
#pragma unroll
    for (int o = 16; o > 0; o >>= 1)
        v += __shfl_xor_sync(0xffffffffu, v, o);
    return v;
}

// ---------------------------------------------------------------------------
// RMSNorm + RoPE + sparse scatter for visual (hidden-state) tokens.
// One warp per (s, h) pair; lane handles dims lane and lane+32.
// Q is pre-scaled by 1/sqrt(HEAD_DIM).
// ---------------------------------------------------------------------------
__global__ void __launch_bounds__(256)
qkv_post_kernel(const float* __restrict__ qr, const float* __restrict__ kr,
                const float* __restrict__ vr,
                const float* __restrict__ gq, const float* __restrict__ gk,
                const float* __restrict__ cosb, const float* __restrict__ sinb,
                float* __restrict__ QA, float* __restrict__ KA,
                float* __restrict__ VA)
{
    const int warp = (blockIdx.x * blockDim.x + threadIdx.x) >> 5;
    const int lane = threadIdx.x & 31;
    const int s = warp >> 4;          // 0..8191
    const int h = warp & 15;
    if (s >= S_LEN) return;

    const size_t src = (size_t)s * INNER + h * HEAD_DIM;
    float q0 = qr[src + lane], q1 = qr[src + lane + 32];
    float k0 = kr[src + lane], k1 = kr[src + lane + 32];
    float v0 = vr[src + lane], v1 = vr[src + lane + 32];

    float rq = rsqrtf(warp_sum32(q0 * q0 + q1 * q1) * (1.f / HEAD_DIM) + EPS_RMS);
    float rk = rsqrtf(warp_sum32(k0 * k0 + k1 * k1) * (1.f / HEAD_DIM) + EPS_RMS);

    q0 *= rq * gq[lane];  q1 *= rq * gq[lane + 32];
    k0 *= rk * gk[lane];  k1 *= rk * gk[lane + 32];

    const float c0 = cosb[(size_t)s * HEAD_DIM + lane];
    const float c1 = cosb[(size_t)s * HEAD_DIM + lane + 32];
    const float s0 = sinb[(size_t)s * HEAD_DIM + lane];
    const float s1 = sinb[(size_t)s * HEAD_DIM + lane + 32];

    // rope: d<32: x*cos - x[d+32]*sin ; d>=32: x*cos + x[d-32]*sin
    const float oq0 = q0 * c0 - q1 * s0;
    const float oq1 = q1 * c1 + q0 * s1;
    const float ok0 = k0 * c0 - k1 * s0;
    const float ok1 = k1 * c1 + k0 * s1;

    const int j = s & 7, tt = s >> 3;
    const size_t dst = (((size_t)(j * NUM_HEADS + h)) * STOT + tt) * HEAD_DIM;
    QA[dst + lane]      = oq0 * ATTN_SCALE;
    QA[dst + lane + 32] = oq1 * ATTN_SCALE;
    KA[dst + lane]      = ok0;
    KA[dst + lane + 32] = ok1;
    VA[dst + lane]      = v0;
    VA[dst + lane + 32] = v1;
}

// ---------------------------------------------------------------------------
// RMSNorm + broadcast-to-8 scatter for text (encoder) tokens. No RoPE.
// ---------------------------------------------------------------------------
__global__ void __launch_bounds__(256)
enc_post_kernel(const float* __restrict__ aqr, const float* __restrict__ akr,
                const float* __restrict__ avr,
                const float* __restrict__ gaq, const float* __restrict__ gak,
                float* __restrict__ QA, float* __restrict__ KA,
                float* __restrict__ VA)
{
    const int warp = (blockIdx.x * blockDim.x + threadIdx.x) >> 5;
    const int lane = threadIdx.x & 31;
    const int tt = warp >> 4;          // 0..255
    const int h  = warp & 15;
    if (tt >= T_LEN) return;

    const size_t src = (size_t)tt * INNER + h * HEAD_DIM;
    float a0 = aqr[src + lane], a1 = aqr[src + lane + 32];
    float b0 = akr[src + lane], b1 = akr[src + lane + 32];
    const float v0 = avr[src + lane], v1 = avr[src + lane + 32];

    float ra = rsqrtf(warp_sum32(a0 * a0 + a1 * a1) * (1.f / HEAD_DIM) + EPS_RMS);
    float rb = rsqrtf(warp_sum32(b0 * b0 + b1 * b1) * (1.f / HEAD_DIM) + EPS_RMS);

    a0 *= ra * gaq[lane] * ATTN_SCALE;  a1 *= ra * gaq[lane + 32] * ATTN_SCALE;
    b0 *= rb * gak[lane];               b1 *= rb * gak[lane + 32];

#pragma unroll
    for (int j = 0; j < SPARSE_N; j++) {
        const size_t dst =
            (((size_t)(j * NUM_HEADS + h)) * STOT + G_LEN + tt) * HEAD_DIM;
        QA[dst + lane] = a0;  QA[dst + lane + 32] = a1;
        KA[dst + lane] = b0;  KA[dst + lane + 32] = b1;
        VA[dst + lane] = v0;  VA[dst + lane + 32] = v1;
    }
}

// ---------------------------------------------------------------------------
// Flash attention: grid (10 q-tiles, 128 jh), 256 threads.
// Q tile 128 rows, key tiles of 64, online softmax, fp32 everywhere.
// Thread layout: tq = t>>3 owns rows tq*4..+3 ; tk = t&7 owns cols tk*8..+7.
// ---------------------------------------------------------------------------
#define ATT_STRIDE 65
#define ATT_BQ 128
#define ATT_BK 64
#define ATT_SMEM_FLOATS (ATT_BQ*ATT_STRIDE + 2*ATT_BK*ATT_STRIDE + ATT_BQ*ATT_STRIDE)
#define ATT_SMEM_BYTES (ATT_SMEM_FLOATS * 4)

__global__ void __launch_bounds__(256)
attn_kernel(const float* __restrict__ QA, const float* __restrict__ KA,
            const float* __restrict__ VA, float* __restrict__ OA)
{
    extern __shared__ float sm[];
    float* Qs = sm;                              // 128 x 65
    float* Ks = Qs + ATT_BQ * ATT_STRIDE;        // 64 x 65
    float* Vs = Ks + ATT_BK * ATT_STRIDE;        // 64 x 65
    float* Ps = Vs + ATT_BK * ATT_STRIDE;        // 128 x 65

    const int t  = threadIdx.x;
    const int jh = blockIdx.y;
    const int q0 = blockIdx.x * ATT_BQ;

    const float* Qg = QA + (size_t)jh * STOT * HEAD_DIM;
    const float* Kg = KA + (size_t)jh * STOT * HEAD_DIM;
    const float* Vg = VA + (size_t)jh * STOT * HEAD_DIM;

    // load Q tile (128x64), float4 granularity: 2048 float4 / 256 thr = 8 each
    for (int idx = t; idx < ATT_BQ * 16; idx += 256) {
        const int r  = idx >> 4;
        const int c4 = (idx & 15) * 4;
        float4 v = *(const float4*)(Qg + (size_t)(q0 + r) * HEAD_DIM + c4);
        Qs[r * ATT_STRIDE + c4 + 0] = v.x;
        Qs[r * ATT_STRIDE + c4 + 1] = v.y;
        Qs[r * ATT_STRIDE + c4 + 2] = v.z;
        Qs[r * ATT_STRIDE + c4 + 3] = v.w;
    }

    const int tq = t >> 3;        // 0..31
    const int tk = t & 7;         // 0..7
    const int r0 = tq * 4;
    const int c0 = tk * 8;

    float m_i[4], l_i[4], acc[4][8];
#pragma unroll
    for (int i = 0; i < 4; i++) {
        m_i[i] = -1e30f;
        l_i[i] = 0.f;
#pragma unroll
        for (int j = 0; j < 8; j++) acc[i][j] = 0.f;
    }

    const int n_ktiles = STOT / ATT_BK;   // 20
    for (int kt = 0; kt < n_ktiles; kt++) {
        const int k0 = kt * ATT_BK;
        // load K,V tiles (each 64x64 = 1024 float4 / 256 thr = 4 each)
        for (int idx = t; idx < ATT_BK * 16; idx += 256) {
            const int r  = idx >> 4;
            const int c4 = (idx & 15) * 4;
            float4 kv = *(const float4*)(Kg + (size_t)(k0 + r) * HEAD_DIM + c4);
            float4 vv = *(const float4*)(Vg + (size_t)(k0 + r) * HEAD_DIM + c4);
            Ks[r * ATT_STRIDE + c4 + 0] = kv.x;
            Ks[r * ATT_STRIDE + c4 + 1] = kv.y;
            Ks[r * ATT_STRIDE + c4 + 2] = kv.z;
            Ks[r * ATT_STRIDE + c4 + 3] = kv.w;
            Vs[r * ATT_STRIDE + c4 + 0] = vv.x;
            Vs[r * ATT_STRIDE + c4 + 1] = vv.y;
            Vs[r * ATT_STRIDE + c4 + 2] = vv.z;
            Vs[r * ATT_STRIDE + c4 + 3] = vv.w;
        }
        __syncthreads();

        // scores: s[i][j] = dot(Q row r0+i, K row c0+j) (Q pre-scaled)
        float sc[4][8];
#pragma unroll
        for (int i = 0; i < 4; i++)
#pragma unroll
            for (int j = 0; j < 8; j++) sc[i][j] = 0.f;

#pragma unroll 8
        for (int d = 0; d < HEAD_DIM; d++) {
            float qv[4], kv[8];
#pragma unroll
            for (int i = 0; i < 4; i++) qv[i] = Qs[(r0 + i) * ATT_STRIDE + d];
#pragma unroll
            for (int j = 0; j < 8; j++) kv[j] = Ks[(c0 + j) * ATT_STRIDE + d];
#pragma unroll
            for (int i = 0; i < 4; i++)
#pragma unroll
                for (int j = 0; j < 8; j++)
                    sc[i][j] += qv[i] * kv[j];
        }

        // online softmax update (row groups of 8 lanes share a row set)
#pragma unroll
        for (int i = 0; i < 4; i++) {
            float mt = sc[i][0];
#pragma unroll
            for (int j = 1; j < 8; j++) mt = fmaxf(mt, sc[i][j]);
            mt = fmaxf(mt, __shfl_xor_sync(0xffffffffu, mt, 1));
            mt = fmaxf(mt, __shfl_xor_sync(0xffffffffu, mt, 2));
            mt = fmaxf(mt, __shfl_xor_sync(0xffffffffu, mt, 4));
            const float mn = fmaxf(m_i[i], mt);
            const float corr = __expf(m_i[i] - mn);
            m_i[i] = mn;
            float rsum = 0.f;
#pragma unroll
            for (int j = 0; j < 8; j++) {
                const float p = __expf(sc[i][j] - mn);
                rsum += p;
                Ps[(r0 + i) * ATT_STRIDE + c0 + j] = p;
            }
            rsum += __shfl_xor_sync(0xffffffffu, rsum, 1);
            rsum += __shfl_xor_sync(0xffffffffu, rsum, 2);
            rsum += __shfl_xor_sync(0xffffffffu, rsum, 4);
            l_i[i] = l_i[i] * corr + rsum;
#pragma unroll
            for (int j = 0; j < 8; j++) acc[i][j] *= corr;
        }
        __syncthreads();

        // PV: acc[i][j] += sum_k Ps[r0+i][k] * Vs[k][c0+j]
#pragma unroll 8
        for (int k = 0; k < ATT_BK; k++) {
            float pv[4], vv[8];
#pragma unroll
            for (int i = 0; i < 4; i++) pv[i] = Ps[(r0 + i) * ATT_STRIDE + k];
#pragma unroll
            for (int j = 0; j < 8; j++) vv[j] = Vs[k * ATT_STRIDE + c0 + j];
#pragma unroll
            for (int i = 0; i < 4; i++)
#pragma unroll
                for (int j = 0; j < 8; j++)
                    acc[i][j] += pv[i] * vv[j];
        }
        __syncthreads();
    }

    float* Og = OA + (size_t)jh * STOT * HEAD_DIM;
#pragma unroll
    for (int i = 0; i < 4; i++) {
        const float inv = 1.f / l_i[i];
        float* op = Og + (size_t)(q0 + r0 + i) * HEAD_DIM + c0;
        float4 o0 = make_float4(acc[i][0]*inv, acc[i][1]*inv, acc[i][2]*inv, acc[i][3]*inv);
        float4 o1 = make_float4(acc[i][4]*inv, acc[i][5]*inv, acc[i][6]*inv, acc[i][7]*inv);
        *(float4*)(op + 0) = o0;
        *(float4*)(op + 4) = o1;
    }
}

// ---------------------------------------------------------------------------
// Gather attention output back to dense layouts for the final GEMMs
// ---------------------------------------------------------------------------
__global__ void __launch_bounds__(256)
gather_vis_kernel(const float* __restrict__ OA, float* __restrict__ vis)
{
    const int idx = blockIdx.x * 256 + threadIdx.x;  // over S_LEN*INNER
    const int s = idx >> 10;
    const int e = idx & 1023;
    const int j = s & 7, tt = s >> 3;
    const int h = e >> 6, d = e & 63;
    vis[idx] = OA[(((size_t)(j * NUM_HEADS + h)) * STOT + tt) * HEAD_DIM + d];
}

__global__ void __launch_bounds__(256)
gather_txt_kernel(const float* __restrict__ OA, float* __restrict__ txt)
{
    const int idx = blockIdx.x * 256 + threadIdx.x;  // over T_LEN*INNER
    const int tt = idx >> 10;
    const int e = idx & 1023;
    const int h = e >> 6, d = e & 63;
    float acc = 0.f;
#pragma unroll
    for (int j = 0; j < SPARSE_N; j++)
        acc += OA[(((size_t)(j * NUM_HEADS + h)) * STOT + G_LEN + tt) * HEAD_DIM + d];
    txt[idx] = acc * (1.f / SPARSE_N);
}

// ---------------------------------------------------------------------------
// kernel_launch
// ---------------------------------------------------------------------------
extern "C" void kernel_launch(void* const* d_in, const int* in_sizes, int n_in,
                              void* d_out, int out_size)
{
    const float* hs   = (const float*)d_in[0];
    const float* enc  = (const float*)d_in[1];
    const float* Wq   = (const float*)d_in[2];
    const float* Wk   = (const float*)d_in[3];
    const float* Wv   = (const float*)d_in[4];
    const float* Waq  = (const float*)d_in[5];
    const float* Wak  = (const float*)d_in[6];
    const float* Wav  = (const float*)d_in[7];
    const float* Wout = (const float*)d_in[8];
    const float* bout = (const float*)d_in[9];
    const float* Waout= (const float*)d_in[10];
    const float* baout= (const float*)d_in[11];
    const float* gq   = (const float*)d_in[12];
    const float* gk   = (const float*)d_in[13];
    const float* gaq  = (const float*)d_in[14];
    const float* gak  = (const float*)d_in[15];
    const float* rc   = (const float*)d_in[16];
    const float* rs   = (const float*)d_in[17];
    float* out = (float*)d_out;

    float *qraw, *kraw, *vraw, *aqraw, *akraw, *avraw;
    float *QA, *KA, *VA, *OA, *vis, *txt;
    cudaGetSymbolAddress((void**)&qraw,  g_qraw);
    cudaGetSymbolAddress((void**)&kraw,  g_kraw);
    cudaGetSymbolAddress((void**)&vraw,  g_vraw);
    cudaGetSymbolAddress((void**)&aqraw, g_aqraw);
    cudaGetSymbolAddress((void**)&akraw, g_akraw);
    cudaGetSymbolAddress((void**)&avraw, g_avraw);
    cudaGetSymbolAddress((void**)&QA,    g_QA);
    cudaGetSymbolAddress((void**)&KA,    g_KA);
    cudaGetSymbolAddress((void**)&VA,    g_VA);
    cudaGetSymbolAddress((void**)&OA,    g_OA);
    cudaGetSymbolAddress((void**)&vis,   g_vis);
    cudaGetSymbolAddress((void**)&txt,   g_txt);

    // 1) projections (NT GEMMs)
    dim3 gBig(INNER / GBN, S_LEN / GBM);   // (8, 64)
    dim3 gEnc(INNER / GBN, T_LEN / GBM);   // (8, 2)
    sgemm_nt_kernel<<<gBig, 256>>>(hs,  Wq,  nullptr, qraw,  S_LEN, INNER, INNER);
    sgemm_nt_kernel<<<gBig, 256>>>(hs,  Wk,  nullptr, kraw,  S_LEN, INNER, INNER);
    sgemm_nt_kernel<<<gBig, 256>>>(hs,  Wv,  nullptr, vraw,  S_LEN, INNER, INNER);
    sgemm_nt_kernel<<<gEnc, 256>>>(enc, Waq, nullptr, aqraw, T_LEN, INNER, INNER);
    sgemm_nt_kernel<<<gEnc, 256>>>(enc, Wak, nullptr, akraw, T_LEN, INNER, INNER);
    sgemm_nt_kernel<<<gEnc, 256>>>(enc, Wav, nullptr, avraw, T_LEN, INNER, INNER);

    // 2) norm + rope + scatter into attention layout
    qkv_post_kernel<<<(S_LEN * NUM_HEADS) / 8, 256>>>(
        qraw, kraw, vraw, gq, gk, rc, rs, QA, KA, VA);
    enc_post_kernel<<<(T_LEN * NUM_HEADS) / 8, 256>>>(
        aqraw, akraw, avraw, gaq, gak, QA, KA, VA);

    // 3) attention
    cudaFuncSetAttribute(attn_kernel,
                         cudaFuncAttributeMaxDynamicSharedMemorySize,
                         ATT_SMEM_BYTES);
    attn_kernel<<<dim3(STOT / ATT_BQ, NJH), 256, ATT_SMEM_BYTES>>>(QA, KA, VA, OA);

    // 4) gather + output projections
    gather_vis_kernel<<<(S_LEN * INNER) / 256, 256>>>(OA, vis);
    gather_txt_kernel<<<(T_LEN * INNER) / 256, 256>>>(OA, txt);
    sgemm_nt_kernel<<<gBig, 256>>>(vis, Wout,  bout,  out,                     S_LEN, INNER, INNER);
    sgemm_nt_kernel<<<gEnc, 256>>>(txt, Waout, baout, out + (size_t)S_LEN * INNER, T_LEN, INNER, INNER);
}

// round 3
// speedup vs baseline: 2.5638x; 2.5638x over previous
#include <cuda_runtime.h>
#include <cuda_bf16.h>
#include <math.h>
#include <stdint.h>

// ---------------------------------------------------------------------------
// Problem constants
// ---------------------------------------------------------------------------
#define S_LEN     8192
#define T_LEN     256
#define NUM_HEADS 16
#define HEAD_DIM  64
#define INNER     1024
#define SPARSE_N  8
#define G_LEN     1024
#define STOT      1280
#define NJH       128
#define EPS_RMS   1e-5f
#define ATTN_SCALE 0.125f
#define ATT_ELEMS (NJH * STOT * HEAD_DIM)   // 10485760

// ---------------------------------------------------------------------------
// Static device scratch
// ---------------------------------------------------------------------------
__device__ float g_qraw[S_LEN * INNER];
__device__ float g_kraw[S_LEN * INNER];
__device__ float g_vraw[S_LEN * INNER];
__device__ float g_aqraw[T_LEN * INNER];
__device__ float g_akraw[T_LEN * INNER];
__device__ float g_avraw[T_LEN * INNER];
__device__ float g_OA[ATT_ELEMS];

__device__ __nv_bfloat16 g_hs_h[S_LEN * INNER];
__device__ __nv_bfloat16 g_hs_l[S_LEN * INNER];
__device__ __nv_bfloat16 g_enc_h[T_LEN * INNER];
__device__ __nv_bfloat16 g_enc_l[T_LEN * INNER];
__device__ __nv_bfloat16 g_w_h[8 * INNER * INNER];   // Wq,Wk,Wv,Waq,Wak,Wav,Wout,Waout
__device__ __nv_bfloat16 g_w_l[8 * INNER * INNER];
__device__ __nv_bfloat16 g_vis_h[S_LEN * INNER];
__device__ __nv_bfloat16 g_vis_l[S_LEN * INNER];
__device__ __nv_bfloat16 g_txt_h[T_LEN * INNER];
__device__ __nv_bfloat16 g_txt_l[T_LEN * INNER];
__device__ __nv_bfloat16 g_QAh[ATT_ELEMS];
__device__ __nv_bfloat16 g_QAl[ATT_ELEMS];
__device__ __nv_bfloat16 g_KAh[ATT_ELEMS];
__device__ __nv_bfloat16 g_KAl[ATT_ELEMS];
__device__ __nv_bfloat16 g_VAh[ATT_ELEMS];
__device__ __nv_bfloat16 g_VAl[ATT_ELEMS];

// ---------------------------------------------------------------------------
// Helpers
// ---------------------------------------------------------------------------
__device__ __forceinline__ uint32_t smem_u32(const void* p) {
    uint32_t a;
    asm("{ .reg .u64 t; cvta.to.shared.u64 t, %1; cvt.u32.u64 %0, t; }"
        : "=r"(a) : "l"(p));
    return a;
}

__device__ __forceinline__ void ldsm_x4(uint32_t* r, uint32_t a) {
    asm volatile("ldmatrix.sync.aligned.m8n8.x4.shared.b16 {%0,%1,%2,%3}, [%4];"
        : "=r"(r[0]), "=r"(r[1]), "=r"(r[2]), "=r"(r[3]) : "r"(a));
}
__device__ __forceinline__ void ldsm_x4_t(uint32_t* r, uint32_t a) {
    asm volatile("ldmatrix.sync.aligned.m8n8.x4.trans.shared.b16 {%0,%1,%2,%3}, [%4];"
        : "=r"(r[0]), "=r"(r[1]), "=r"(r[2]), "=r"(r[3]) : "r"(a));
}
__device__ __forceinline__ void mma16816(float* c, const uint32_t* a, const uint32_t* b) {
    asm volatile(
        "mma.sync.aligned.m16n8k16.row.col.f32.bf16.bf16.f32 "
        "{%0,%1,%2,%3}, {%4,%5,%6,%7}, {%8,%9}, {%0,%1,%2,%3};"
        : "+f"(c[0]), "+f"(c[1]), "+f"(c[2]), "+f"(c[3])
        : "r"(a[0]), "r"(a[1]), "r"(a[2]), "r"(a[3]), "r"(b[0]), "r"(b[1]));
}

__device__ __forceinline__ uint32_t packbf(__nv_bfloat16 x, __nv_bfloat16 y) {
    return (uint32_t)__bfloat16_as_ushort(x) | ((uint32_t)__bfloat16_as_ushort(y) << 16);
}

__device__ __forceinline__ void split2(float x, float y, uint32_t& hi, uint32_t& lo) {
    __nv_bfloat16 hx = __float2bfloat16(x), hy = __float2bfloat16(y);
    __nv_bfloat16 lx = __float2bfloat16(x - __bfloat162float(hx));
    __nv_bfloat16 ly = __float2bfloat16(y - __bfloat162float(hy));
    hi = packbf(hx, hy);
    lo = packbf(lx, ly);
}

__device__ __forceinline__ void store_split(__nv_bfloat16* ph, __nv_bfloat16* pl,
                                            size_t idx, float v) {
    __nv_bfloat16 h = __float2bfloat16(v);
    ph[idx] = h;
    pl[idx] = __float2bfloat16(v - __bfloat162float(h));
}

__device__ __forceinline__ float warp_sum32(float v) {
#pragma unroll
    for (int o = 16; o > 0; o >>= 1)
        v += __shfl_xor_sync(0xffffffffu, v, o);
    return v;
}

// ---------------------------------------------------------------------------
// fp32 -> bf16 hi/lo conversion (vectorized x4)
// ---------------------------------------------------------------------------
__global__ void __launch_bounds__(256)
cvt_kernel(const float* __restrict__ src, __nv_bfloat16* __restrict__ hi,
           __nv_bfloat16* __restrict__ lo, int n4)
{
    const int i = blockIdx.x * 256 + threadIdx.x;
    if (i >= n4) return;
    float4 v = ((const float4*)src)[i];
    uint32_t h01, l01, h23, l23;
    split2(v.x, v.y, h01, l01);
    split2(v.z, v.w, h23, l23);
    ((uint2*)hi)[i] = make_uint2(h01, h23);
    ((uint2*)lo)[i] = make_uint2(l01, l23);
}

// ---------------------------------------------------------------------------
// bf16x3 tensor-core GEMM (NT): C[m][n] = sum_k A[m][k]*W[n][k] (+bias)
// 128x128 CTA tile, BK=32, 8 warps (4x2), warp tile 32x64.
// ---------------------------------------------------------------------------
#define PADK 40   // row stride (bf16 elems); 80B -> conflict-free ldmatrix

__global__ void __launch_bounds__(256, 2)
gemm_bf3_kernel(const __nv_bfloat16* __restrict__ Ah, const __nv_bfloat16* __restrict__ Al,
                const __nv_bfloat16* __restrict__ Wh, const __nv_bfloat16* __restrict__ Wl,
                const float* __restrict__ bias, float* __restrict__ C,
                int M, int N, int K)
{
    __shared__ __nv_bfloat16 sm[4 * 128 * PADK];
    const int t    = threadIdx.x;
    const int lane = t & 31;
    const int wid  = t >> 5;
    const int wm   = wid >> 1;     // 0..3
    const int wn   = wid & 1;      // 0..1
    const int m0   = blockIdx.y * 128;
    const int n0   = blockIdx.x * 128;

    float acc[2][8][4];
#pragma unroll
    for (int i = 0; i < 2; i++)
#pragma unroll
        for (int j = 0; j < 8; j++)
#pragma unroll
            for (int q = 0; q < 4; q++) acc[i][j][q] = 0.f;

    const int lrow = t >> 1;           // 0..127
    const int lcol = (t & 1) * 16;     // 0 or 16

    const __nv_bfloat16* gAh = Ah + (size_t)(m0 + lrow) * K + lcol;
    const __nv_bfloat16* gAl = Al + (size_t)(m0 + lrow) * K + lcol;
    const __nv_bfloat16* gWh = Wh + (size_t)(n0 + lrow) * K + lcol;
    const __nv_bfloat16* gWl = Wl + (size_t)(n0 + lrow) * K + lcol;

    __nv_bfloat16* sAh = sm;
    __nv_bfloat16* sAl = sm + 128 * PADK;
    __nv_bfloat16* sWh = sm + 2 * 128 * PADK;
    __nv_bfloat16* sWl = sm + 3 * 128 * PADK;
    __nv_bfloat16* const sdst = sm + lrow * PADK + lcol;

    const uint32_t smb = smem_u32(sm);
    // A frag base: row = wm*32 + (lane&15), col = (lane>>4)*8
    const uint32_t abase = smb + (((wm * 32 + (lane & 15)) * PADK + ((lane >> 4) << 3)) << 1);
    // B frag base: row = wn*64 + (lane&7) + (lane>>4)*8, col = ((lane>>3)&1)*8
    const uint32_t bbase = smb + ((2 * 128 * PADK +
                     (wn * 64 + (lane & 7) + ((lane >> 4) << 3)) * PADK +
                     (((lane >> 3) & 1) << 3)) << 1);

    for (int k0 = 0; k0 < K; k0 += 32) {
        *(uint4*)(sdst)                       = *(const uint4*)(gAh + k0);
        *(uint4*)(sdst + 8)                   = *(const uint4*)(gAh + k0 + 8);
        *(uint4*)(sdst + 128 * PADK)          = *(const uint4*)(gAl + k0);
        *(uint4*)(sdst + 128 * PADK + 8)      = *(const uint4*)(gAl + k0 + 8);
        *(uint4*)(sdst + 2 * 128 * PADK)      = *(const uint4*)(gWh + k0);
        *(uint4*)(sdst + 2 * 128 * PADK + 8)  = *(const uint4*)(gWh + k0 + 8);
        *(uint4*)(sdst + 3 * 128 * PADK)      = *(const uint4*)(gWl + k0);
        *(uint4*)(sdst + 3 * 128 * PADK + 8)  = *(const uint4*)(gWl + k0 + 8);
        __syncthreads();

#pragma unroll
        for (int pass = 0; pass < 3; pass++) {
            const uint32_t ab = abase + (pass == 2 ? (128 * PADK * 2) : 0);
            const uint32_t bb = bbase + (pass == 1 ? (128 * PADK * 2) : 0);
#pragma unroll
            for (int ks = 0; ks < 32; ks += 16) {
                uint32_t a0[4], a1[4];
                ldsm_x4(a0, ab + ks * 2);
                ldsm_x4(a1, ab + ks * 2 + 16 * PADK * 2);
#pragma unroll
                for (int nbp = 0; nbp < 4; nbp++) {
                    uint32_t b[4];
                    ldsm_x4(b, bb + ks * 2 + nbp * 16 * PADK * 2);
                    mma16816(acc[0][2 * nbp],     a0, b);
                    mma16816(acc[0][2 * nbp + 1], a0, b + 2);
                    mma16816(acc[1][2 * nbp],     a1, b);
                    mma16816(acc[1][2 * nbp + 1], a1, b + 2);
                }
            }
        }
        __syncthreads();
    }

    const int r0 = m0 + wm * 32 + (lane >> 2);
    const int c0 = n0 + wn * 64 + (lane & 3) * 2;
#pragma unroll
    for (int mi = 0; mi < 2; mi++) {
        const int r = r0 + mi * 16;
#pragma unroll
        for (int nb = 0; nb < 8; nb++) {
            const int c = c0 + nb * 8;
            float b0 = 0.f, b1 = 0.f;
            if (bias) { b0 = bias[c]; b1 = bias[c + 1]; }
            *(float2*)(C + (size_t)r * N + c) =
                make_float2(acc[mi][nb][0] + b0, acc[mi][nb][1] + b1);
            *(float2*)(C + (size_t)(r + 8) * N + c) =
                make_float2(acc[mi][nb][2] + b0, acc[mi][nb][3] + b1);
        }
    }
}

// ---------------------------------------------------------------------------
// RMSNorm + RoPE + sparse scatter (visual) -> bf16 hi/lo attention layout
// ---------------------------------------------------------------------------
__global__ void __launch_bounds__(256)
qkv_post_kernel(const float* __restrict__ qr, const float* __restrict__ kr,
                const float* __restrict__ vr,
                const float* __restrict__ gq, const float* __restrict__ gk,
                const float* __restrict__ cosb, const float* __restrict__ sinb,
                __nv_bfloat16* __restrict__ QAh, __nv_bfloat16* __restrict__ QAl,
                __nv_bfloat16* __restrict__ KAh, __nv_bfloat16* __restrict__ KAl,
                __nv_bfloat16* __restrict__ VAh, __nv_bfloat16* __restrict__ VAl)
{
    const int warp = (blockIdx.x * blockDim.x + threadIdx.x) >> 5;
    const int lane = threadIdx.x & 31;
    const int s = warp >> 4;
    const int h = warp & 15;
    if (s >= S_LEN) return;

    const size_t src = (size_t)s * INNER + h * HEAD_DIM;
    float q0 = qr[src + lane], q1 = qr[src + lane + 32];
    float k0 = kr[src + lane], k1 = kr[src + lane + 32];
    float v0 = vr[src + lane], v1 = vr[src + lane + 32];

    float rq = rsqrtf(warp_sum32(q0 * q0 + q1 * q1) * (1.f / HEAD_DIM) + EPS_RMS);
    float rk = rsqrtf(warp_sum32(k0 * k0 + k1 * k1) * (1.f / HEAD_DIM) + EPS_RMS);

    q0 *= rq * gq[lane];  q1 *= rq * gq[lane + 32];
    k0 *= rk * gk[lane];  k1 *= rk * gk[lane + 32];

    const float c0 = cosb[(size_t)s * HEAD_DIM + lane];
    const float c1 = cosb[(size_t)s * HEAD_DIM + lane + 32];
    const float s0 = sinb[(size_t)s * HEAD_DIM + lane];
    const float s1 = sinb[(size_t)s * HEAD_DIM + lane + 32];

    const float oq0 = (q0 * c0 - q1 * s0) * ATTN_SCALE;
    const float oq1 = (q1 * c1 + q0 * s1) * ATTN_SCALE;
    const float ok0 = k0 * c0 - k1 * s0;
    const float ok1 = k1 * c1 + k0 * s1;

    const int j = s & 7, tt = s >> 3;
    const size_t dst = (((size_t)(j * NUM_HEADS + h)) * STOT + tt) * HEAD_DIM;
    store_split(QAh, QAl, dst + lane,      oq0);
    store_split(QAh, QAl, dst + lane + 32, oq1);
    store_split(KAh, KAl, dst + lane,      ok0);
    store_split(KAh, KAl, dst + lane + 32, ok1);
    store_split(VAh, VAl, dst + lane,      v0);
    store_split(VAh, VAl, dst + lane + 32, v1);
}

// ---------------------------------------------------------------------------
// RMSNorm + broadcast scatter (text) -> bf16 hi/lo
// ---------------------------------------------------------------------------
__global__ void __launch_bounds__(256)
enc_post_kernel(const float* __restrict__ aqr, const float* __restrict__ akr,
                const float* __restrict__ avr,
                const float* __restrict__ gaq, const float* __restrict__ gak,
                __nv_bfloat16* __restrict__ QAh, __nv_bfloat16* __restrict__ QAl,
                __nv_bfloat16* __restrict__ KAh, __nv_bfloat16* __restrict__ KAl,
                __nv_bfloat16* __restrict__ VAh, __nv_bfloat16* __restrict__ VAl)
{
    const int warp = (blockIdx.x * blockDim.x + threadIdx.x) >> 5;
    const int lane = threadIdx.x & 31;
    const int tt = warp >> 4;
    const int h  = warp & 15;
    if (tt >= T_LEN) return;

    const size_t src = (size_t)tt * INNER + h * HEAD_DIM;
    float a0 = aqr[src + lane], a1 = aqr[src + lane + 32];
    float b0 = akr[src + lane], b1 = akr[src + lane + 32];
    const float v0 = avr[src + lane], v1 = avr[src + lane + 32];

    float ra = rsqrtf(warp_sum32(a0 * a0 + a1 * a1) * (1.f / HEAD_DIM) + EPS_RMS);
    float rb = rsqrtf(warp_sum32(b0 * b0 + b1 * b1) * (1.f / HEAD_DIM) + EPS_RMS);

    a0 *= ra * gaq[lane] * ATTN_SCALE;  a1 *= ra * gaq[lane + 32] * ATTN_SCALE;
    b0 *= rb * gak[lane];               b1 *= rb * gak[lane + 32];

#pragma unroll
    for (int j = 0; j < SPARSE_N; j++) {
        const size_t dst =
            (((size_t)(j * NUM_HEADS + h)) * STOT + G_LEN + tt) * HEAD_DIM;
        store_split(QAh, QAl, dst + lane,      a0);
        store_split(QAh, QAl, dst + lane + 32, a1);
        store_split(KAh, KAl, dst + lane,      b0);
        store_split(KAh, KAl, dst + lane + 32, b1);
        store_split(VAh, VAl, dst + lane,      v0);
        store_split(VAh, VAl, dst + lane + 32, v1);
    }
}

// ---------------------------------------------------------------------------
// Flash attention with bf16x3 mma.sync
// grid (10, 128), 256 threads (8 warps x 16 q-rows), BK=64
// ---------------------------------------------------------------------------
#define APAD 72
#define QH_O 0
#define QL_O (128 * APAD)
#define KH_O (2 * 128 * APAD)
#define KL_O (KH_O + 64 * APAD)
#define VH_O (KL_O + 64 * APAD)
#define VL_O (VH_O + 64 * APAD)
#define ATT_SM_BYTES ((VL_O + 64 * APAD) * 2)   // 73728

__global__ void __launch_bounds__(256, 1)
attn_mma_kernel(const __nv_bfloat16* __restrict__ Qhg, const __nv_bfloat16* __restrict__ Qlg,
                const __nv_bfloat16* __restrict__ Khg, const __nv_bfloat16* __restrict__ Klg,
                const __nv_bfloat16* __restrict__ Vhg, const __nv_bfloat16* __restrict__ Vlg,
                float* __restrict__ OA)
{
    extern __shared__ __nv_bfloat16 smA[];
    const int t    = threadIdx.x;
    const int lane = t & 31;
    const int w    = t >> 5;
    const int jh   = blockIdx.y;
    const int q0   = blockIdx.x * 128;
    const size_t base = (size_t)jh * STOT * HEAD_DIM;

    // load Q tile 128x64 (hi+lo)
    {
        const int row = t >> 1, c0 = (t & 1) * 32;
        const __nv_bfloat16* gh = Qhg + base + (size_t)(q0 + row) * 64 + c0;
        const __nv_bfloat16* gl = Qlg + base + (size_t)(q0 + row) * 64 + c0;
        __nv_bfloat16* sh = smA + QH_O + row * APAD + c0;
        __nv_bfloat16* sl = smA + QL_O + row * APAD + c0;
#pragma unroll
        for (int c = 0; c < 32; c += 8) {
            *(uint4*)(sh + c) = *(const uint4*)(gh + c);
            *(uint4*)(sl + c) = *(const uint4*)(gl + c);
        }
    }

    float o[8][4];
#pragma unroll
    for (int i = 0; i < 8; i++)
#pragma unroll
        for (int j = 0; j < 4; j++) o[i][j] = 0.f;
    float m0r = -1e30f, m1r = -1e30f, l0r = 0.f, l1r = 0.f;

    const uint32_t smb = smem_u32(smA);
    const uint32_t qfrag = smb + ((QH_O + (w * 16 + (lane & 15)) * APAD + ((lane >> 4) << 3)) << 1);
    const uint32_t kfrag = smb + ((KH_O + ((lane & 7) + ((lane >> 4) << 3)) * APAD + (((lane >> 3) & 1) << 3)) << 1);
    const uint32_t vfrag = smb + ((VH_O + ((lane & 7) + (((lane >> 3) & 1) << 3)) * APAD + ((lane >> 4) << 3)) << 1);

    const int krow = t >> 2, kc0 = (t & 3) * 16;

    for (int kt = 0; kt < 20; kt++) {
        const size_t g = base + (size_t)(kt * 64 + krow) * 64 + kc0;
        __nv_bfloat16* dK = smA + KH_O + krow * APAD + kc0;
        __nv_bfloat16* dV = smA + VH_O + krow * APAD + kc0;
        *(uint4*)(dK)                     = *(const uint4*)(Khg + g);
        *(uint4*)(dK + 8)                 = *(const uint4*)(Khg + g + 8);
        *(uint4*)(dK + 64 * APAD)         = *(const uint4*)(Klg + g);
        *(uint4*)(dK + 64 * APAD + 8)     = *(const uint4*)(Klg + g + 8);
        *(uint4*)(dV)                     = *(const uint4*)(Vhg + g);
        *(uint4*)(dV + 8)                 = *(const uint4*)(Vhg + g + 8);
        *(uint4*)(dV + 64 * APAD)         = *(const uint4*)(Vlg + g);
        *(uint4*)(dV + 64 * APAD + 8)     = *(const uint4*)(Vlg + g + 8);
        __syncthreads();

        // ---- scores: S[16 x 64] per warp, 3-pass bf16 ----
        float s[8][4];
#pragma unroll
        for (int i = 0; i < 8; i++)
#pragma unroll
            for (int j = 0; j < 4; j++) s[i][j] = 0.f;

#pragma unroll
        for (int pass = 0; pass < 3; pass++) {
            const uint32_t qb = qfrag + (pass == 2 ? ((QL_O - QH_O) << 1) : 0);
            const uint32_t kb = kfrag + (pass == 1 ? ((KL_O - KH_O) << 1) : 0);
#pragma unroll
            for (int ks = 0; ks < 64; ks += 16) {
                uint32_t a[4];
                ldsm_x4(a, qb + ks * 2);
#pragma unroll
                for (int nbp = 0; nbp < 4; nbp++) {
                    uint32_t b[4];
                    ldsm_x4(b, kb + ks * 2 + nbp * 16 * APAD * 2);
                    mma16816(s[2 * nbp],     a, b);
                    mma16816(s[2 * nbp + 1], a, b + 2);
                }
            }
        }

        // ---- online softmax (rows r=l>>2 and r+8) ----
        float mt0 = -1e30f, mt1 = -1e30f;
#pragma unroll
        for (int nb = 0; nb < 8; nb++) {
            mt0 = fmaxf(mt0, fmaxf(s[nb][0], s[nb][1]));
            mt1 = fmaxf(mt1, fmaxf(s[nb][2], s[nb][3]));
        }
        mt0 = fmaxf(mt0, __shfl_xor_sync(0xffffffffu, mt0, 1));
        mt0 = fmaxf(mt0, __shfl_xor_sync(0xffffffffu, mt0, 2));
        mt1 = fmaxf(mt1, __shfl_xor_sync(0xffffffffu, mt1, 1));
        mt1 = fmaxf(mt1, __shfl_xor_sync(0xffffffffu, mt1, 2));
        const float mn0 = fmaxf(m0r, mt0), mn1 = fmaxf(m1r, mt1);
        const float cf0 = __expf(m0r - mn0), cf1 = __expf(m1r - mn1);
        m0r = mn0;  m1r = mn1;
        float rs0 = 0.f, rs1 = 0.f;
#pragma unroll
        for (int nb = 0; nb < 8; nb++) {
            s[nb][0] = __expf(s[nb][0] - mn0);  rs0 += s[nb][0];
            s[nb][1] = __expf(s[nb][1] - mn0);  rs0 += s[nb][1];
            s[nb][2] = __expf(s[nb][2] - mn1);  rs1 += s[nb][2];
            s[nb][3] = __expf(s[nb][3] - mn1);  rs1 += s[nb][3];
        }
        rs0 += __shfl_xor_sync(0xffffffffu, rs0, 1);
        rs0 += __shfl_xor_sync(0xffffffffu, rs0, 2);
        rs1 += __shfl_xor_sync(0xffffffffu, rs1, 1);
        rs1 += __shfl_xor_sync(0xffffffffu, rs1, 2);
        l0r = l0r * cf0 + rs0;
        l1r = l1r * cf1 + rs1;
#pragma unroll
        for (int db = 0; db < 8; db++) {
            o[db][0] *= cf0;  o[db][1] *= cf0;
            o[db][2] *= cf1;  o[db][3] *= cf1;
        }

        // ---- PV: O[16 x 64] += P * V, 3-pass bf16 ----
#pragma unroll
        for (int kb2 = 0; kb2 < 4; kb2++) {
            uint32_t ph[4], pl[4];
            split2(s[2 * kb2][0],     s[2 * kb2][1],     ph[0], pl[0]);
            split2(s[2 * kb2][2],     s[2 * kb2][3],     ph[1], pl[1]);
            split2(s[2 * kb2 + 1][0], s[2 * kb2 + 1][1], ph[2], pl[2]);
            split2(s[2 * kb2 + 1][2], s[2 * kb2 + 1][3], ph[3], pl[3]);
            const uint32_t vb = vfrag + kb2 * 16 * APAD * 2;
#pragma unroll
            for (int dbp = 0; dbp < 4; dbp++) {
                uint32_t vh4[4], vl4[4];
                ldsm_x4_t(vh4, vb + dbp * 16 * 2);
                ldsm_x4_t(vl4, vb + ((VL_O - VH_O) << 1) + dbp * 16 * 2);
                mma16816(o[2 * dbp],     ph, vh4);
                mma16816(o[2 * dbp + 1], ph, vh4 + 2);
                mma16816(o[2 * dbp],     ph, vl4);
                mma16816(o[2 * dbp + 1], ph, vl4 + 2);
                mma16816(o[2 * dbp],     pl, vh4);
                mma16816(o[2 * dbp + 1], pl, vh4 + 2);
            }
        }
        __syncthreads();
    }

    const float inv0 = 1.f / l0r, inv1 = 1.f / l1r;
    const int row = q0 + w * 16 + (lane >> 2);
    const int col = (lane & 3) * 2;
#pragma unroll
    for (int db = 0; db < 8; db++) {
        *(float2*)(OA + base + (size_t)row * 64 + db * 8 + col) =
            make_float2(o[db][0] * inv0, o[db][1] * inv0);
        *(float2*)(OA + base + (size_t)(row + 8) * 64 + db * 8 + col) =
            make_float2(o[db][2] * inv1, o[db][3] * inv1);
    }
}

// ---------------------------------------------------------------------------
// Gather kernels -> bf16 hi/lo dense layouts
// ---------------------------------------------------------------------------
__global__ void __launch_bounds__(256)
gather_vis_kernel(const float* __restrict__ OA,
                  __nv_bfloat16* __restrict__ vh, __nv_bfloat16* __restrict__ vl)
{
    const int i = blockIdx.x * 256 + threadIdx.x;   // over S_LEN*INNER/4
    const int idx = i * 4;
    const int s = idx >> 10, e = idx & 1023;
    const int j = s & 7, tt = s >> 3;
    const int h = e >> 6, d = e & 63;
    float4 v = *(const float4*)(OA + (((size_t)(j * NUM_HEADS + h)) * STOT + tt) * HEAD_DIM + d);
    uint32_t h01, l01, h23, l23;
    split2(v.x, v.y, h01, l01);
    split2(v.z, v.w, h23, l23);
    ((uint2*)vh)[i] = make_uint2(h01, h23);
    ((uint2*)vl)[i] = make_uint2(l01, l23);
}

__global__ void __launch_bounds__(256)
gather_txt_kernel(const float* __restrict__ OA,
                  __nv_bfloat16* __restrict__ th, __nv_bfloat16* __restrict__ tl)
{
    const int i = blockIdx.x * 256 + threadIdx.x;   // over T_LEN*INNER/4
    const int idx = i * 4;
    const int tt = idx >> 10, e = idx & 1023;
    const int h = e >> 6, d = e & 63;
    float4 acc = make_float4(0.f, 0.f, 0.f, 0.f);
#pragma unroll
    for (int j = 0; j < SPARSE_N; j++) {
        float4 v = *(const float4*)(OA +
            (((size_t)(j * NUM_HEADS + h)) * STOT + G_LEN + tt) * HEAD_DIM + d);
        acc.x += v.x; acc.y += v.y; acc.z += v.z; acc.w += v.w;
    }
    acc.x *= 0.125f; acc.y *= 0.125f; acc.z *= 0.125f; acc.w *= 0.125f;
    uint32_t h01, l01, h23, l23;
    split2(acc.x, acc.y, h01, l01);
    split2(acc.z, acc.w, h23, l23);
    ((uint2*)th)[i] = make_uint2(h01, h23);
    ((uint2*)tl)[i] = make_uint2(l01, l23);
}

// ---------------------------------------------------------------------------
// kernel_launch
// ---------------------------------------------------------------------------
extern "C" void kernel_launch(void* const* d_in, const int* in_sizes, int n_in,
                              void* d_out, int out_size)
{
    const float* hs   = (const float*)d_in[0];
    const float* enc  = (const float*)d_in[1];
    const float* Wsrc[8] = { (const float*)d_in[2], (const float*)d_in[3],
                             (const float*)d_in[4], (const float*)d_in[5],
                             (const float*)d_in[6], (const float*)d_in[7],
                             (const float*)d_in[8], (const float*)d_in[10] };
    const float* bout  = (const float*)d_in[9];
    const float* baout = (const float*)d_in[11];
    const float* gq   = (const float*)d_in[12];
    const float* gk   = (const float*)d_in[13];
    const float* gaq  = (const float*)d_in[14];
    const float* gak  = (const float*)d_in[15];
    const float* rc   = (const float*)d_in[16];
    const float* rs   = (const float*)d_in[17];
    float* out = (float*)d_out;

    float *qraw, *kraw, *vraw, *aqraw, *akraw, *avraw, *OA;
    __nv_bfloat16 *hs_h, *hs_l, *enc_h, *enc_l, *w_h, *w_l;
    __nv_bfloat16 *vis_h, *vis_l, *txt_h, *txt_l;
    __nv_bfloat16 *QAh, *QAl, *KAh, *KAl, *VAh, *VAl;
    cudaGetSymbolAddress((void**)&qraw,  g_qraw);
    cudaGetSymbolAddress((void**)&kraw,  g_kraw);
    cudaGetSymbolAddress((void**)&vraw,  g_vraw);
    cudaGetSymbolAddress((void**)&aqraw, g_aqraw);
    cudaGetSymbolAddress((void**)&akraw, g_akraw);
    cudaGetSymbolAddress((void**)&avraw, g_avraw);
    cudaGetSymbolAddress((void**)&OA,    g_OA);
    cudaGetSymbolAddress((void**)&hs_h,  g_hs_h);
    cudaGetSymbolAddress((void**)&hs_l,  g_hs_l);
    cudaGetSymbolAddress((void**)&enc_h, g_enc_h);
    cudaGetSymbolAddress((void**)&enc_l, g_enc_l);
    cudaGetSymbolAddress((void**)&w_h,   g_w_h);
    cudaGetSymbolAddress((void**)&w_l,   g_w_l);
    cudaGetSymbolAddress((void**)&vis_h, g_vis_h);
    cudaGetSymbolAddress((void**)&vis_l, g_vis_l);
    cudaGetSymbolAddress((void**)&txt_h, g_txt_h);
    cudaGetSymbolAddress((void**)&txt_l, g_txt_l);
    cudaGetSymbolAddress((void**)&QAh,   g_QAh);
    cudaGetSymbolAddress((void**)&QAl,   g_QAl);
    cudaGetSymbolAddress((void**)&KAh,   g_KAh);
    cudaGetSymbolAddress((void**)&KAl,   g_KAl);
    cudaGetSymbolAddress((void**)&VAh,   g_VAh);
    cudaGetSymbolAddress((void**)&VAl,   g_VAl);

    cudaFuncSetAttribute(attn_mma_kernel,
                         cudaFuncAttributeMaxDynamicSharedMemorySize, ATT_SM_BYTES);

    // 0) convert inputs to bf16 hi/lo
    cvt_kernel<<<(S_LEN * INNER / 4 + 255) / 256, 256>>>(hs,  hs_h,  hs_l,  S_LEN * INNER / 4);
    cvt_kernel<<<(T_LEN * INNER / 4 + 255) / 256, 256>>>(enc, enc_h, enc_l, T_LEN * INNER / 4);
    for (int i = 0; i < 8; i++)
        cvt_kernel<<<(INNER * INNER / 4 + 255) / 256, 256>>>(
            Wsrc[i], w_h + (size_t)i * INNER * INNER, w_l + (size_t)i * INNER * INNER,
            INNER * INNER / 4);

    const size_t WS = (size_t)INNER * INNER;
    dim3 gBig(INNER / 128, S_LEN / 128);   // (8, 64)
    dim3 gEnc(INNER / 128, T_LEN / 128);   // (8, 2)

    // 1) projections
    gemm_bf3_kernel<<<gBig, 256>>>(hs_h,  hs_l,  w_h + 0 * WS, w_l + 0 * WS, nullptr, qraw,  S_LEN, INNER, INNER);
    gemm_bf3_kernel<<<gBig, 256>>>(hs_h,  hs_l,  w_h + 1 * WS, w_l + 1 * WS, nullptr, kraw,  S_LEN, INNER, INNER);
    gemm_bf3_kernel<<<gBig, 256>>>(hs_h,  hs_l,  w_h + 2 * WS, w_l + 2 * WS, nullptr, vraw,  S_LEN, INNER, INNER);
    gemm_bf3_kernel<<<gEnc, 256>>>(enc_h, enc_l, w_h + 3 * WS, w_l + 3 * WS, nullptr, aqraw, T_LEN, INNER, INNER);
    gemm_bf3_kernel<<<gEnc, 256>>>(enc_h, enc_l, w_h + 4 * WS, w_l + 4 * WS, nullptr, akraw, T_LEN, INNER, INNER);
    gemm_bf3_kernel<<<gEnc, 256>>>(enc_h, enc_l, w_h + 5 * WS, w_l + 5 * WS, nullptr, avraw, T_LEN, INNER, INNER);

    // 2) norm + rope + scatter (bf16 hi/lo out)
    qkv_post_kernel<<<(S_LEN * NUM_HEADS) / 8, 256>>>(
        qraw, kraw, vraw, gq, gk, rc, rs, QAh, QAl, KAh, KAl, VAh, VAl);
    enc_post_kernel<<<(T_LEN * NUM_HEADS) / 8, 256>>>(
        aqraw, akraw, avraw, gaq, gak, QAh, QAl, KAh, KAl, VAh, VAl);

    // 3) attention
    attn_mma_kernel<<<dim3(STOT / 128, NJH), 256, ATT_SM_BYTES>>>(
        QAh, QAl, KAh, KAl, VAh, VAl, OA);

    // 4) gather + output projections
    gather_vis_kernel<<<(S_LEN * INNER / 4) / 256, 256>>>(OA, vis_h, vis_l);
    gather_txt_kernel<<<(T_LEN * INNER / 4) / 256, 256>>>(OA, txt_h, txt_l);
    gemm_bf3_kernel<<<gBig, 256>>>(vis_h, vis_l, w_h + 6 * WS, w_l + 6 * WS, bout,  out, S_LEN, INNER, INNER);
    gemm_bf3_kernel<<<gEnc, 256>>>(txt_h, txt_l, w_h + 7 * WS, w_l + 7 * WS, baout,
                                   out + (size_t)S_LEN * INNER, T_LEN, INNER, INNER);
}

// round 4
// speedup vs baseline: 3.5703x; 1.3926x over previous
#include <cuda_runtime.h>
#include <cuda_bf16.h>
#include <math.h>
#include <stdint.h>

// ---------------------------------------------------------------------------
// Problem constants
// ---------------------------------------------------------------------------
#define S_LEN     8192
#define T_LEN     256
#define NUM_HEADS 16
#define HEAD_DIM  64
#define INNER     1024
#define INNER3    3072
#define SPARSE_N  8
#define G_LEN     1024
#define STOT      1280
#define NJH       128
#define EPS_RMS   1e-5f
#define ATTN_SCALE 0.125f
#define ATT_ELEMS (NJH * STOT * HEAD_DIM)

// ---------------------------------------------------------------------------
// Static device scratch
// ---------------------------------------------------------------------------
__device__ float g_qkvraw[S_LEN * INNER3];
__device__ float g_aqkvraw[T_LEN * INNER3];
__device__ float g_OA[ATT_ELEMS];

__device__ __nv_bfloat16 g_hs_h[S_LEN * INNER];
__device__ __nv_bfloat16 g_hs_l[S_LEN * INNER];
__device__ __nv_bfloat16 g_enc_h[T_LEN * INNER];
__device__ __nv_bfloat16 g_enc_l[T_LEN * INNER];
__device__ __nv_bfloat16 g_w_h[8 * INNER * INNER];
__device__ __nv_bfloat16 g_w_l[8 * INNER * INNER];
__device__ __nv_bfloat16 g_vis_h[S_LEN * INNER];
__device__ __nv_bfloat16 g_vis_l[S_LEN * INNER];
__device__ __nv_bfloat16 g_txt_h[T_LEN * INNER];
__device__ __nv_bfloat16 g_txt_l[T_LEN * INNER];
__device__ __nv_bfloat16 g_QAh[ATT_ELEMS];
__device__ __nv_bfloat16 g_QAl[ATT_ELEMS];
__device__ __nv_bfloat16 g_KAh[ATT_ELEMS];
__device__ __nv_bfloat16 g_KAl[ATT_ELEMS];
__device__ __nv_bfloat16 g_VAh[ATT_ELEMS];
__device__ __nv_bfloat16 g_VAl[ATT_ELEMS];

// ---------------------------------------------------------------------------
// Helpers
// ---------------------------------------------------------------------------
__device__ __forceinline__ uint32_t smem_u32(const void* p) {
    uint32_t a;
    asm("{ .reg .u64 t; cvta.to.shared.u64 t, %1; cvt.u32.u64 %0, t; }"
        : "=r"(a) : "l"(p));
    return a;
}

#define CP_ASYNC16(dst, src) \
    asm volatile("cp.async.cg.shared.global [%0], [%1], 16;" :: "r"(dst), "l"(src))
#define CP_COMMIT() asm volatile("cp.async.commit_group;" ::: "memory")
#define CP_WAIT0()  asm volatile("cp.async.wait_group 0;" ::: "memory")
#define CP_WAIT1()  asm volatile("cp.async.wait_group 1;" ::: "memory")

__device__ __forceinline__ void ldsm_x4(uint32_t* r, uint32_t a) {
    asm volatile("ldmatrix.sync.aligned.m8n8.x4.shared.b16 {%0,%1,%2,%3}, [%4];"
        : "=r"(r[0]), "=r"(r[1]), "=r"(r[2]), "=r"(r[3]) : "r"(a));
}
__device__ __forceinline__ void ldsm_x4_t(uint32_t* r, uint32_t a) {
    asm volatile("ldmatrix.sync.aligned.m8n8.x4.trans.shared.b16 {%0,%1,%2,%3}, [%4];"
        : "=r"(r[0]), "=r"(r[1]), "=r"(r[2]), "=r"(r[3]) : "r"(a));
}
__device__ __forceinline__ void mma16816(float* c, const uint32_t* a, const uint32_t* b) {
    asm volatile(
        "mma.sync.aligned.m16n8k16.row.col.f32.bf16.bf16.f32 "
        "{%0,%1,%2,%3}, {%4,%5,%6,%7}, {%8,%9}, {%0,%1,%2,%3};"
        : "+f"(c[0]), "+f"(c[1]), "+f"(c[2]), "+f"(c[3])
        : "r"(a[0]), "r"(a[1]), "r"(a[2]), "r"(a[3]), "r"(b[0]), "r"(b[1]));
}

__device__ __forceinline__ uint32_t packbf(__nv_bfloat16 x, __nv_bfloat16 y) {
    return (uint32_t)__bfloat16_as_ushort(x) | ((uint32_t)__bfloat16_as_ushort(y) << 16);
}
__device__ __forceinline__ void split2(float x, float y, uint32_t& hi, uint32_t& lo) {
    __nv_bfloat16 hx = __float2bfloat16(x), hy = __float2bfloat16(y);
    __nv_bfloat16 lx = __float2bfloat16(x - __bfloat162float(hx));
    __nv_bfloat16 ly = __float2bfloat16(y - __bfloat162float(hy));
    hi = packbf(hx, hy);
    lo = packbf(lx, ly);
}
__device__ __forceinline__ void store_split(__nv_bfloat16* ph, __nv_bfloat16* pl,
                                            size_t idx, float v) {
    __nv_bfloat16 h = __float2bfloat16(v);
    ph[idx] = h;
    pl[idx] = __float2bfloat16(v - __bfloat162float(h));
}
__device__ __forceinline__ float warp_sum32(float v) {
#pragma unroll
    for (int o = 16; o > 0; o >>= 1)
        v += __shfl_xor_sync(0xffffffffu, v, o);
    return v;
}

// ---------------------------------------------------------------------------
// fp32 -> bf16 hi/lo conversion
// ---------------------------------------------------------------------------
__global__ void __launch_bounds__(256)
cvt_kernel(const float* __restrict__ src, __nv_bfloat16* __restrict__ hi,
           __nv_bfloat16* __restrict__ lo, int n4)
{
    const int i = blockIdx.x * 256 + threadIdx.x;
    if (i >= n4) return;
    float4 v = ((const float4*)src)[i];
    uint32_t h01, l01, h23, l23;
    split2(v.x, v.y, h01, l01);
    split2(v.z, v.w, h23, l23);
    ((uint2*)hi)[i] = make_uint2(h01, h23);
    ((uint2*)lo)[i] = make_uint2(l01, l23);
}

// ---------------------------------------------------------------------------
// bf16x3 tensor-core GEMM (NT) with cp.async 2-stage pipeline.
// C[m][n] = sum_k A[m][k]*W[n][k] (+bias). 128x128 CTA, BK=32, 8 warps.
// ---------------------------------------------------------------------------
#define PADK 40
#define GT_TILE  (128 * PADK)          // elems per (sub)tile
#define GT_STAGE (4 * GT_TILE)         // Ahi,Alo,Whi,Wlo
#define GEMM_SMEM_BYTES (2 * GT_STAGE * 2)

__global__ void __launch_bounds__(256, 2)
gemm_bf3_kernel(const __nv_bfloat16* __restrict__ Ah, const __nv_bfloat16* __restrict__ Al,
                const __nv_bfloat16* __restrict__ Wh, const __nv_bfloat16* __restrict__ Wl,
                const float* __restrict__ bias, float* __restrict__ C,
                int M, int N, int K)
{
    extern __shared__ __nv_bfloat16 sm[];
    const int t    = threadIdx.x;
    const int lane = t & 31;
    const int wid  = t >> 5;
    const int wm   = wid >> 1;
    const int wn   = wid & 1;
    const int m0   = blockIdx.y * 128;
    const int n0   = blockIdx.x * 128;

    float acc[2][8][4];
#pragma unroll
    for (int i = 0; i < 2; i++)
#pragma unroll
        for (int j = 0; j < 8; j++)
#pragma unroll
            for (int q = 0; q < 4; q++) acc[i][j][q] = 0.f;

    // loader mapping: tile = t>>6 (0:Ah 1:Al 2:Wh 3:Wl), 64 threads/tile,
    // 8 chunks of 16B each: chunk c = l64 + i*64; row = c>>2, col = (c&3)*8
    const int tile = t >> 6;
    const int l64  = t & 63;
    const int lrr  = l64 >> 2;          // 0..15
    const int lcc  = (l64 & 3) * 8;     // 0,8,16,24
    const __nv_bfloat16* gsrc =
        (tile == 0) ? Ah : (tile == 1) ? Al : (tile == 2) ? Wh : Wl;
    const int rowbase = (tile < 2) ? m0 : n0;
    const uint32_t smb = smem_u32(sm);
    const uint32_t sdst0 = smb + ((tile * GT_TILE + lrr * PADK + lcc) << 1);
    const __nv_bfloat16* gp = gsrc + (size_t)(rowbase + lrr) * K + lcc;

    // frag bases (byte offsets within a stage)
    const uint32_t abase_rel = (((wm * 32 + (lane & 15)) * PADK + ((lane >> 4) << 3)) << 1);
    const uint32_t bbase_rel = ((2 * GT_TILE +
                     (wn * 64 + (lane & 7) + ((lane >> 4) << 3)) * PADK +
                     (((lane >> 3) & 1) << 3)) << 1);

    const int NT = K / 32;

    // prologue: stage 0
    {
        const __nv_bfloat16* g = gp;
#pragma unroll
        for (int i = 0; i < 8; i++) {
            CP_ASYNC16(sdst0 + (uint32_t)((i * 16 * PADK) << 1),
                       g + (size_t)(i * 16) * K);
        }
        CP_COMMIT();
    }

    for (int kt = 0; kt < NT; kt++) {
        const int b = kt & 1;
        if (kt + 1 < NT) {
            const __nv_bfloat16* g = gp + (kt + 1) * 32;
            const uint32_t d = sdst0 + (uint32_t)((((kt + 1) & 1) * GT_STAGE) << 1);
#pragma unroll
            for (int i = 0; i < 8; i++) {
                CP_ASYNC16(d + (uint32_t)((i * 16 * PADK) << 1),
                           g + (size_t)(i * 16) * K);
            }
            CP_COMMIT();
            CP_WAIT1();
        } else {
            CP_WAIT0();
        }
        __syncthreads();

        const uint32_t stage = smb + (uint32_t)((b * GT_STAGE) << 1);
        const uint32_t abase = stage + abase_rel;
        const uint32_t bbase = stage + bbase_rel;
#pragma unroll
        for (int pass = 0; pass < 3; pass++) {
            const uint32_t ab = abase + (pass == 2 ? (GT_TILE << 1) : 0);
            const uint32_t bb = bbase + (pass == 1 ? (GT_TILE << 1) : 0);
#pragma unroll
            for (int ks = 0; ks < 32; ks += 16) {
                uint32_t a0[4], a1[4];
                ldsm_x4(a0, ab + ks * 2);
                ldsm_x4(a1, ab + ks * 2 + 16 * PADK * 2);
#pragma unroll
                for (int nbp = 0; nbp < 4; nbp++) {
                    uint32_t bfr[4];
                    ldsm_x4(bfr, bb + ks * 2 + nbp * 16 * PADK * 2);
                    mma16816(acc[0][2 * nbp],     a0, bfr);
                    mma16816(acc[0][2 * nbp + 1], a0, bfr + 2);
                    mma16816(acc[1][2 * nbp],     a1, bfr);
                    mma16816(acc[1][2 * nbp + 1], a1, bfr + 2);
                }
            }
        }
        __syncthreads();
    }

    const int r0 = m0 + wm * 32 + (lane >> 2);
    const int c0 = n0 + wn * 64 + (lane & 3) * 2;
#pragma unroll
    for (int mi = 0; mi < 2; mi++) {
        const int r = r0 + mi * 16;
#pragma unroll
        for (int nb = 0; nb < 8; nb++) {
            const int c = c0 + nb * 8;
            float b0 = 0.f, b1 = 0.f;
            if (bias) { b0 = bias[c]; b1 = bias[c + 1]; }
            *(float2*)(C + (size_t)r * N + c) =
                make_float2(acc[mi][nb][0] + b0, acc[mi][nb][1] + b1);
            *(float2*)(C + (size_t)(r + 8) * N + c) =
                make_float2(acc[mi][nb][2] + b0, acc[mi][nb][3] + b1);
        }
    }
}

// ---------------------------------------------------------------------------
// RMSNorm + RoPE + sparse scatter (visual)  [reads merged qkv buffer]
// ---------------------------------------------------------------------------
__global__ void __launch_bounds__(256)
qkv_post_kernel(const float* __restrict__ qkv,
                const float* __restrict__ gq, const float* __restrict__ gk,
                const float* __restrict__ cosb, const float* __restrict__ sinb,
                __nv_bfloat16* __restrict__ QAh, __nv_bfloat16* __restrict__ QAl,
                __nv_bfloat16* __restrict__ KAh, __nv_bfloat16* __restrict__ KAl,
                __nv_bfloat16* __restrict__ VAh, __nv_bfloat16* __restrict__ VAl)
{
    const int warp = (blockIdx.x * blockDim.x + threadIdx.x) >> 5;
    const int lane = threadIdx.x & 31;
    const int s = warp >> 4;
    const int h = warp & 15;
    if (s >= S_LEN) return;

    const size_t src = (size_t)s * INNER3 + h * HEAD_DIM;
    float q0 = qkv[src + lane],            q1 = qkv[src + lane + 32];
    float k0 = qkv[src + INNER + lane],    k1 = qkv[src + INNER + lane + 32];
    float v0 = qkv[src + 2*INNER + lane],  v1 = qkv[src + 2*INNER + lane + 32];

    float rq = rsqrtf(warp_sum32(q0 * q0 + q1 * q1) * (1.f / HEAD_DIM) + EPS_RMS);
    float rk = rsqrtf(warp_sum32(k0 * k0 + k1 * k1) * (1.f / HEAD_DIM) + EPS_RMS);

    q0 *= rq * gq[lane];  q1 *= rq * gq[lane + 32];
    k0 *= rk * gk[lane];  k1 *= rk * gk[lane + 32];

    const float c0 = cosb[(size_t)s * HEAD_DIM + lane];
    const float c1 = cosb[(size_t)s * HEAD_DIM + lane + 32];
    const float s0 = sinb[(size_t)s * HEAD_DIM + lane];
    const float s1 = sinb[(size_t)s * HEAD_DIM + lane + 32];

    const float oq0 = (q0 * c0 - q1 * s0) * ATTN_SCALE;
    const float oq1 = (q1 * c1 + q0 * s1) * ATTN_SCALE;
    const float ok0 = k0 * c0 - k1 * s0;
    const float ok1 = k1 * c1 + k0 * s1;

    const int j = s & 7, tt = s >> 3;
    const size_t dst = (((size_t)(j * NUM_HEADS + h)) * STOT + tt) * HEAD_DIM;
    store_split(QAh, QAl, dst + lane,      oq0);
    store_split(QAh, QAl, dst + lane + 32, oq1);
    store_split(KAh, KAl, dst + lane,      ok0);
    store_split(KAh, KAl, dst + lane + 32, ok1);
    store_split(VAh, VAl, dst + lane,      v0);
    store_split(VAh, VAl, dst + lane + 32, v1);
}

// ---------------------------------------------------------------------------
// RMSNorm + broadcast scatter (text)  [reads merged enc qkv buffer]
// ---------------------------------------------------------------------------
__global__ void __launch_bounds__(256)
enc_post_kernel(const float* __restrict__ aqkv,
                const float* __restrict__ gaq, const float* __restrict__ gak,
                __nv_bfloat16* __restrict__ QAh, __nv_bfloat16* __restrict__ QAl,
                __nv_bfloat16* __restrict__ KAh, __nv_bfloat16* __restrict__ KAl,
                __nv_bfloat16* __restrict__ VAh, __nv_bfloat16* __restrict__ VAl)
{
    const int warp = (blockIdx.x * blockDim.x + threadIdx.x) >> 5;
    const int lane = threadIdx.x & 31;
    const int tt = warp >> 4;
    const int h  = warp & 15;
    if (tt >= T_LEN) return;

    const size_t src = (size_t)tt * INNER3 + h * HEAD_DIM;
    float a0 = aqkv[src + lane],           a1 = aqkv[src + lane + 32];
    float b0 = aqkv[src + INNER + lane],   b1 = aqkv[src + INNER + lane + 32];
    const float v0 = aqkv[src + 2*INNER + lane], v1 = aqkv[src + 2*INNER + lane + 32];

    float ra = rsqrtf(warp_sum32(a0 * a0 + a1 * a1) * (1.f / HEAD_DIM) + EPS_RMS);
    float rb = rsqrtf(warp_sum32(b0 * b0 + b1 * b1) * (1.f / HEAD_DIM) + EPS_RMS);

    a0 *= ra * gaq[lane] * ATTN_SCALE;  a1 *= ra * gaq[lane + 32] * ATTN_SCALE;
    b0 *= rb * gak[lane];               b1 *= rb * gak[lane + 32];

#pragma unroll
    for (int j = 0; j < SPARSE_N; j++) {
        const size_t dst =
            (((size_t)(j * NUM_HEADS + h)) * STOT + G_LEN + tt) * HEAD_DIM;
        store_split(QAh, QAl, dst + lane,      a0);
        store_split(QAh, QAl, dst + lane + 32, a1);
        store_split(KAh, KAl, dst + lane,      b0);
        store_split(KAh, KAl, dst + lane + 32, b1);
        store_split(VAh, VAl, dst + lane,      v0);
        store_split(VAh, VAl, dst + lane + 32, v1);
    }
}

// ---------------------------------------------------------------------------
// Flash attention with bf16x3 mma.sync + cp.async double-buffered K/V
// grid (10, 128), 256 threads (8 warps x 16 q-rows), BK=64
// ---------------------------------------------------------------------------
#define APAD 72
#define AQ_ELEMS (2 * 128 * APAD)
#define KV_TILE  (64 * APAD)
#define KV_STAGE (4 * KV_TILE)
#define ATT_SM_BYTES ((AQ_ELEMS + 2 * KV_STAGE) * 2)   // 110592

__global__ void __launch_bounds__(256, 1)
attn_mma_kernel(const __nv_bfloat16* __restrict__ Qhg, const __nv_bfloat16* __restrict__ Qlg,
                const __nv_bfloat16* __restrict__ Khg, const __nv_bfloat16* __restrict__ Klg,
                const __nv_bfloat16* __restrict__ Vhg, const __nv_bfloat16* __restrict__ Vlg,
                float* __restrict__ OA)
{
    extern __shared__ __nv_bfloat16 smA[];
    const int t    = threadIdx.x;
    const int lane = t & 31;
    const int w    = t >> 5;
    const int jh   = blockIdx.y;
    const int q0   = blockIdx.x * 128;
    const size_t base = (size_t)jh * STOT * HEAD_DIM;

    const uint32_t smb = smem_u32(smA);

    // KV loader mapping: tile = t>>6 (0:Kh 1:Kl 2:Vh 3:Vl), 64 threads/tile,
    // 8 chunks each: chunk c = l64 + i*64; row = c>>3, col = (c&7)*8
    const int tile = t >> 6;
    const int l64  = t & 63;
    const int krr  = l64 >> 3;          // 0..7
    const int kcc  = (l64 & 7) * 8;     // 0..56
    const __nv_bfloat16* kvsrc =
        (tile == 0) ? Khg : (tile == 1) ? Klg : (tile == 2) ? Vhg : Vlg;
    const uint32_t kvdst0 = smb + ((AQ_ELEMS + tile * KV_TILE + krr * APAD + kcc) << 1);

    // prologue: KV stage 0
    {
        const __nv_bfloat16* g = kvsrc + base + (size_t)krr * 64 + kcc;
#pragma unroll
        for (int i = 0; i < 8; i++)
            CP_ASYNC16(kvdst0 + (uint32_t)((i * 8 * APAD) << 1),
                       g + (size_t)(i * 8) * 64);
        CP_COMMIT();
    }

    // Q tile (synchronous loads, overlap with async stage 0)
    {
        const int row = t >> 1, c0 = (t & 1) * 32;
        const __nv_bfloat16* gh = Qhg + base + (size_t)(q0 + row) * 64 + c0;
        const __nv_bfloat16* gl = Qlg + base + (size_t)(q0 + row) * 64 + c0;
        __nv_bfloat16* sh = smA + row * APAD + c0;
        __nv_bfloat16* sl = smA + 128 * APAD + row * APAD + c0;
#pragma unroll
        for (int c = 0; c < 32; c += 8) {
            *(uint4*)(sh + c) = *(const uint4*)(gh + c);
            *(uint4*)(sl + c) = *(const uint4*)(gl + c);
        }
    }

    float o[8][4];
#pragma unroll
    for (int i = 0; i < 8; i++)
#pragma unroll
        for (int j = 0; j < 4; j++) o[i][j] = 0.f;
    float m0r = -1e30f, m1r = -1e30f, l0r = 0.f, l1r = 0.f;

    const uint32_t qfrag = smb + (((w * 16 + (lane & 15)) * APAD + ((lane >> 4) << 3)) << 1);
    const uint32_t kfrag_rel = ((((lane & 7) + ((lane >> 4) << 3)) * APAD + (((lane >> 3) & 1) << 3)) << 1);
    const uint32_t vfrag_rel = (((2 * KV_TILE) + ((lane & 7) + (((lane >> 3) & 1) << 3)) * APAD + ((lane >> 4) << 3)) << 1);

    for (int kt = 0; kt < 20; kt++) {
        const int b = kt & 1;
        if (kt + 1 < 20) {
            const __nv_bfloat16* g = kvsrc + base + (size_t)((kt + 1) * 64 + krr) * 64 + kcc;
            const uint32_t d = kvdst0 + (uint32_t)((((kt + 1) & 1) * KV_STAGE) << 1);
#pragma unroll
            for (int i = 0; i < 8; i++)
                CP_ASYNC16(d + (uint32_t)((i * 8 * APAD) << 1),
                           g + (size_t)(i * 8) * 64);
            CP_COMMIT();
            CP_WAIT1();
        } else {
            CP_WAIT0();
        }
        __syncthreads();

        const uint32_t kvstage = smb + (uint32_t)(((AQ_ELEMS + b * KV_STAGE)) << 1);
        const uint32_t kfrag = kvstage + kfrag_rel;
        const uint32_t vfrag = kvstage + vfrag_rel;

        // ---- scores: S[16 x 64] per warp, 3-pass bf16 ----
        float s[8][4];
#pragma unroll
        for (int i = 0; i < 8; i++)
#pragma unroll
            for (int j = 0; j < 4; j++) s[i][j] = 0.f;

#pragma unroll
        for (int pass = 0; pass < 3; pass++) {
            const uint32_t qb = qfrag + (pass == 2 ? ((128 * APAD) << 1) : 0);
            const uint32_t kb = kfrag + (pass == 1 ? (KV_TILE << 1) : 0);
#pragma unroll
            for (int ks = 0; ks < 64; ks += 16) {
                uint32_t a[4];
                ldsm_x4(a, qb + ks * 2);
#pragma unroll
                for (int nbp = 0; nbp < 4; nbp++) {
                    uint32_t bfr[4];
                    ldsm_x4(bfr, kb + ks * 2 + nbp * 16 * APAD * 2);
                    mma16816(s[2 * nbp],     a, bfr);
                    mma16816(s[2 * nbp + 1], a, bfr + 2);
                }
            }
        }

        // ---- online softmax ----
        float mt0 = -1e30f, mt1 = -1e30f;
#pragma unroll
        for (int nb = 0; nb < 8; nb++) {
            mt0 = fmaxf(mt0, fmaxf(s[nb][0], s[nb][1]));
            mt1 = fmaxf(mt1, fmaxf(s[nb][2], s[nb][3]));
        }
        mt0 = fmaxf(mt0, __shfl_xor_sync(0xffffffffu, mt0, 1));
        mt0 = fmaxf(mt0, __shfl_xor_sync(0xffffffffu, mt0, 2));
        mt1 = fmaxf(mt1, __shfl_xor_sync(0xffffffffu, mt1, 1));
        mt1 = fmaxf(mt1, __shfl_xor_sync(0xffffffffu, mt1, 2));
        const float mn0 = fmaxf(m0r, mt0), mn1 = fmaxf(m1r, mt1);
        const float cf0 = __expf(m0r - mn0), cf1 = __expf(m1r - mn1);
        m0r = mn0;  m1r = mn1;
        float rs0 = 0.f, rs1 = 0.f;
#pragma unroll
        for (int nb = 0; nb < 8; nb++) {
            s[nb][0] = __expf(s[nb][0] - mn0);  rs0 += s[nb][0];
            s[nb][1] = __expf(s[nb][1] - mn0);  rs0 += s[nb][1];
            s[nb][2] = __expf(s[nb][2] - mn1);  rs1 += s[nb][2];
            s[nb][3] = __expf(s[nb][3] - mn1);  rs1 += s[nb][3];
        }
        rs0 += __shfl_xor_sync(0xffffffffu, rs0, 1);
        rs0 += __shfl_xor_sync(0xffffffffu, rs0, 2);
        rs1 += __shfl_xor_sync(0xffffffffu, rs1, 1);
        rs1 += __shfl_xor_sync(0xffffffffu, rs1, 2);
        l0r = l0r * cf0 + rs0;
        l1r = l1r * cf1 + rs1;
#pragma unroll
        for (int db = 0; db < 8; db++) {
            o[db][0] *= cf0;  o[db][1] *= cf0;
            o[db][2] *= cf1;  o[db][3] *= cf1;
        }

        // ---- PV: O += P * V, 3-pass bf16 ----
#pragma unroll
        for (int kb2 = 0; kb2 < 4; kb2++) {
            uint32_t ph[4], pl[4];
            split2(s[2 * kb2][0],     s[2 * kb2][1],     ph[0], pl[0]);
            split2(s[2 * kb2][2],     s[2 * kb2][3],     ph[1], pl[1]);
            split2(s[2 * kb2 + 1][0], s[2 * kb2 + 1][1], ph[2], pl[2]);
            split2(s[2 * kb2 + 1][2], s[2 * kb2 + 1][3], ph[3], pl[3]);
            const uint32_t vb = vfrag + kb2 * 16 * APAD * 2;
#pragma unroll
            for (int dbp = 0; dbp < 4; dbp++) {
                uint32_t vh4[4], vl4[4];
                ldsm_x4_t(vh4, vb + dbp * 16 * 2);
                ldsm_x4_t(vl4, vb + (KV_TILE << 1) + dbp * 16 * 2);
                mma16816(o[2 * dbp],     ph, vh4);
                mma16816(o[2 * dbp + 1], ph, vh4 + 2);
                mma16816(o[2 * dbp],     ph, vl4);
                mma16816(o[2 * dbp + 1], ph, vl4 + 2);
                mma16816(o[2 * dbp],     pl, vh4);
                mma16816(o[2 * dbp + 1], pl, vh4 + 2);
            }
        }
        __syncthreads();
    }

    const float inv0 = 1.f / l0r, inv1 = 1.f / l1r;
    const int row = q0 + w * 16 + (lane >> 2);
    const int col = (lane & 3) * 2;
#pragma unroll
    for (int db = 0; db < 8; db++) {
        *(float2*)(OA + base + (size_t)row * 64 + db * 8 + col) =
            make_float2(o[db][0] * inv0, o[db][1] * inv0);
        *(float2*)(OA + base + (size_t)(row + 8) * 64 + db * 8 + col) =
            make_float2(o[db][2] * inv1, o[db][3] * inv1);
    }
}

// ---------------------------------------------------------------------------
// Gather kernels -> bf16 hi/lo dense layouts
// ---------------------------------------------------------------------------
__global__ void __launch_bounds__(256)
gather_vis_kernel(const float* __restrict__ OA,
                  __nv_bfloat16* __restrict__ vh, __nv_bfloat16* __restrict__ vl)
{
    const int i = blockIdx.x * 256 + threadIdx.x;
    const int idx = i * 4;
    const int s = idx >> 10, e = idx & 1023;
    const int j = s & 7, tt = s >> 3;
    const int h = e >> 6, d = e & 63;
    float4 v = *(const float4*)(OA + (((size_t)(j * NUM_HEADS + h)) * STOT + tt) * HEAD_DIM + d);
    uint32_t h01, l01, h23, l23;
    split2(v.x, v.y, h01, l01);
    split2(v.z, v.w, h23, l23);
    ((uint2*)vh)[i] = make_uint2(h01, h23);
    ((uint2*)vl)[i] = make_uint2(l01, l23);
}

__global__ void __launch_bounds__(256)
gather_txt_kernel(const float* __restrict__ OA,
                  __nv_bfloat16* __restrict__ th, __nv_bfloat16* __restrict__ tl)
{
    const int i = blockIdx.x * 256 + threadIdx.x;
    const int idx = i * 4;
    const int tt = idx >> 10, e = idx & 1023;
    const int h = e >> 6, d = e & 63;
    float4 acc = make_float4(0.f, 0.f, 0.f, 0.f);
#pragma unroll
    for (int j = 0; j < SPARSE_N; j++) {
        float4 v = *(const float4*)(OA +
            (((size_t)(j * NUM_HEADS + h)) * STOT + G_LEN + tt) * HEAD_DIM + d);
        acc.x += v.x; acc.y += v.y; acc.z += v.z; acc.w += v.w;
    }
    acc.x *= 0.125f; acc.y *= 0.125f; acc.z *= 0.125f; acc.w *= 0.125f;
    uint32_t h01, l01, h23, l23;
    split2(acc.x, acc.y, h01, l01);
    split2(acc.z, acc.w, h23, l23);
    ((uint2*)th)[i] = make_uint2(h01, h23);
    ((uint2*)tl)[i] = make_uint2(l01, l23);
}

// ---------------------------------------------------------------------------
// kernel_launch
// ---------------------------------------------------------------------------
extern "C" void kernel_launch(void* const* d_in, const int* in_sizes, int n_in,
                              void* d_out, int out_size)
{
    const float* hs   = (const float*)d_in[0];
    const float* enc  = (const float*)d_in[1];
    const float* Wsrc[8] = { (const float*)d_in[2], (const float*)d_in[3],
                             (const float*)d_in[4], (const float*)d_in[5],
                             (const float*)d_in[6], (const float*)d_in[7],
                             (const float*)d_in[8], (const float*)d_in[10] };
    const float* bout  = (const float*)d_in[9];
    const float* baout = (const float*)d_in[11];
    const float* gq   = (const float*)d_in[12];
    const float* gk   = (const float*)d_in[13];
    const float* gaq  = (const float*)d_in[14];
    const float* gak  = (const float*)d_in[15];
    const float* rc   = (const float*)d_in[16];
    const float* rs   = (const float*)d_in[17];
    float* out = (float*)d_out;

    float *qkvraw, *aqkvraw, *OA;
    __nv_bfloat16 *hs_h, *hs_l, *enc_h, *enc_l, *w_h, *w_l;
    __nv_bfloat16 *vis_h, *vis_l, *txt_h, *txt_l;
    __nv_bfloat16 *QAh, *QAl, *KAh, *KAl, *VAh, *VAl;
    cudaGetSymbolAddress((void**)&qkvraw,  g_qkvraw);
    cudaGetSymbolAddress((void**)&aqkvraw, g_aqkvraw);
    cudaGetSymbolAddress((void**)&OA,    g_OA);
    cudaGetSymbolAddress((void**)&hs_h,  g_hs_h);
    cudaGetSymbolAddress((void**)&hs_l,  g_hs_l);
    cudaGetSymbolAddress((void**)&enc_h, g_enc_h);
    cudaGetSymbolAddress((void**)&enc_l, g_enc_l);
    cudaGetSymbolAddress((void**)&w_h,   g_w_h);
    cudaGetSymbolAddress((void**)&w_l,   g_w_l);
    cudaGetSymbolAddress((void**)&vis_h, g_vis_h);
    cudaGetSymbolAddress((void**)&vis_l, g_vis_l);
    cudaGetSymbolAddress((void**)&txt_h, g_txt_h);
    cudaGetSymbolAddress((void**)&txt_l, g_txt_l);
    cudaGetSymbolAddress((void**)&QAh,   g_QAh);
    cudaGetSymbolAddress((void**)&QAl,   g_QAl);
    cudaGetSymbolAddress((void**)&KAh,   g_KAh);
    cudaGetSymbolAddress((void**)&KAl,   g_KAl);
    cudaGetSymbolAddress((void**)&VAh,   g_VAh);
    cudaGetSymbolAddress((void**)&VAl,   g_VAl);

    cudaFuncSetAttribute(gemm_bf3_kernel,
                         cudaFuncAttributeMaxDynamicSharedMemorySize, GEMM_SMEM_BYTES);
    cudaFuncSetAttribute(attn_mma_kernel,
                         cudaFuncAttributeMaxDynamicSharedMemorySize, ATT_SM_BYTES);

    // 0) convert inputs to bf16 hi/lo
    cvt_kernel<<<(S_LEN * INNER / 4 + 255) / 256, 256>>>(hs,  hs_h,  hs_l,  S_LEN * INNER / 4);
    cvt_kernel<<<(T_LEN * INNER / 4 + 255) / 256, 256>>>(enc, enc_h, enc_l, T_LEN * INNER / 4);
    for (int i = 0; i < 8; i++)
        cvt_kernel<<<(INNER * INNER / 4 + 255) / 256, 256>>>(
            Wsrc[i], w_h + (size_t)i * INNER * INNER, w_l + (size_t)i * INNER * INNER,
            INNER * INNER / 4);

    const size_t WS = (size_t)INNER * INNER;

    // 1) merged projections (N = 3072)
    dim3 gBig3(INNER3 / 128, S_LEN / 128);   // (24, 64)
    dim3 gEnc3(INNER3 / 128, T_LEN / 128);   // (24, 2)
    gemm_bf3_kernel<<<gBig3, 256, GEMM_SMEM_BYTES>>>(
        hs_h, hs_l, w_h + 0 * WS, w_l + 0 * WS, nullptr, qkvraw, S_LEN, INNER3, INNER);
    gemm_bf3_kernel<<<gEnc3, 256, GEMM_SMEM_BYTES>>>(
        enc_h, enc_l, w_h + 3 * WS, w_l + 3 * WS, nullptr, aqkvraw, T_LEN, INNER3, INNER);

    // 2) norm + rope + scatter
    qkv_post_kernel<<<(S_LEN * NUM_HEADS) / 8, 256>>>(
        qkvraw, gq, gk, rc, rs, QAh, QAl, KAh, KAl, VAh, VAl);
    enc_post_kernel<<<(T_LEN * NUM_HEADS) / 8, 256>>>(
        aqkvraw, gaq, gak, QAh, QAl, KAh, KAl, VAh, VAl);

    // 3) attention
    attn_mma_kernel<<<dim3(STOT / 128, NJH), 256, ATT_SM_BYTES>>>(
        QAh, QAl, KAh, KAl, VAh, VAl, OA);

    // 4) gather + output projections
    dim3 gBig(INNER / 128, S_LEN / 128);   // (8, 64)
    dim3 gEnc(INNER / 128, T_LEN / 128);   // (8, 2)
    gather_vis_kernel<<<(S_LEN * INNER / 4) / 256, 256>>>(OA, vis_h, vis_l);
    gather_txt_kernel<<<(T_LEN * INNER / 4) / 256, 256>>>(OA, txt_h, txt_l);
    gemm_bf3_kernel<<<gBig, 256, GEMM_SMEM_BYTES>>>(
        vis_h, vis_l, w_h + 6 * WS, w_l + 6 * WS, bout, out, S_LEN, INNER, INNER);
    gemm_bf3_kernel<<<gEnc, 256, GEMM_SMEM_BYTES>>>(
        txt_h, txt_l, w_h + 7 * WS, w_l + 7 * WS, baout,
        out + (size_t)S_LEN * INNER, T_LEN, INNER, INNER);
}

// round 5
// speedup vs baseline: 3.7649x; 1.0545x over previous
#include <cuda_runtime.h>
#include <cuda_bf16.h>
#include <math.h>
#include <stdint.h>

// ---------------------------------------------------------------------------
// Problem constants
// ---------------------------------------------------------------------------
#define S_LEN     8192
#define T_LEN     256
#define NUM_HEADS 16
#define HEAD_DIM  64
#define INNER     1024
#define INNER3    3072
#define SPARSE_N  8
#define G_LEN     1024
#define STOT      1280
#define NJH       128
#define EPS_RMS   1e-5f
#define ATTN_SCALE 0.125f
#define ATT_ELEMS (NJH * STOT * HEAD_DIM)

// ---------------------------------------------------------------------------
// Static device scratch
// ---------------------------------------------------------------------------
__device__ float g_qkvraw[S_LEN * INNER3];
__device__ float g_aqkvraw[T_LEN * INNER3];
__device__ float g_OA[ATT_ELEMS];

__device__ __nv_bfloat16 g_hs_h[S_LEN * INNER];
__device__ __nv_bfloat16 g_hs_l[S_LEN * INNER];
__device__ __nv_bfloat16 g_enc_h[T_LEN * INNER];
__device__ __nv_bfloat16 g_enc_l[T_LEN * INNER];
__device__ __nv_bfloat16 g_w_h[8 * INNER * INNER];
__device__ __nv_bfloat16 g_w_l[8 * INNER * INNER];
__device__ __nv_bfloat16 g_vis_h[S_LEN * INNER];
__device__ __nv_bfloat16 g_vis_l[S_LEN * INNER];
__device__ __nv_bfloat16 g_txt_h[T_LEN * INNER];
__device__ __nv_bfloat16 g_txt_l[T_LEN * INNER];
__device__ __nv_bfloat16 g_QAh[ATT_ELEMS];
__device__ __nv_bfloat16 g_QAl[ATT_ELEMS];
__device__ __nv_bfloat16 g_KAh[ATT_ELEMS];
__device__ __nv_bfloat16 g_KAl[ATT_ELEMS];
__device__ __nv_bfloat16 g_VAh[ATT_ELEMS];
__device__ __nv_bfloat16 g_VAl[ATT_ELEMS];

// ---------------------------------------------------------------------------
// Helpers
// ---------------------------------------------------------------------------
__device__ __forceinline__ uint32_t smem_u32(const void* p) {
    uint32_t a;
    asm("{ .reg .u64 t; cvta.to.shared.u64 t, %1; cvt.u32.u64 %0, t; }"
        : "=r"(a) : "l"(p));
    return a;
}

#define CP_ASYNC16(dst, src) \
    asm volatile("cp.async.cg.shared.global [%0], [%1], 16;" :: "r"(dst), "l"(src))
#define CP_COMMIT() asm volatile("cp.async.commit_group;" ::: "memory")
#define CP_WAIT0()  asm volatile("cp.async.wait_group 0;" ::: "memory")
#define CP_WAIT1()  asm volatile("cp.async.wait_group 1;" ::: "memory")

__device__ __forceinline__ void ldsm_x4(uint32_t* r, uint32_t a) {
    asm volatile("ldmatrix.sync.aligned.m8n8.x4.shared.b16 {%0,%1,%2,%3}, [%4];"
        : "=r"(r[0]), "=r"(r[1]), "=r"(r[2]), "=r"(r[3]) : "r"(a));
}
__device__ __forceinline__ void ldsm_x4_t(uint32_t* r, uint32_t a) {
    asm volatile("ldmatrix.sync.aligned.m8n8.x4.trans.shared.b16 {%0,%1,%2,%3}, [%4];"
        : "=r"(r[0]), "=r"(r[1]), "=r"(r[2]), "=r"(r[3]) : "r"(a));
}
__device__ __forceinline__ void mma16816(float* c, const uint32_t* a, const uint32_t* b) {
    asm volatile(
        "mma.sync.aligned.m16n8k16.row.col.f32.bf16.bf16.f32 "
        "{%0,%1,%2,%3}, {%4,%5,%6,%7}, {%8,%9}, {%0,%1,%2,%3};"
        : "+f"(c[0]), "+f"(c[1]), "+f"(c[2]), "+f"(c[3])
        : "r"(a[0]), "r"(a[1]), "r"(a[2]), "r"(a[3]), "r"(b[0]), "r"(b[1]));
}

__device__ __forceinline__ uint32_t packbf(__nv_bfloat16 x, __nv_bfloat16 y) {
    return (uint32_t)__bfloat16_as_ushort(x) | ((uint32_t)__bfloat16_as_ushort(y) << 16);
}
__device__ __forceinline__ void split2(float x, float y, uint32_t& hi, uint32_t& lo) {
    __nv_bfloat16 hx = __float2bfloat16(x), hy = __float2bfloat16(y);
    __nv_bfloat16 lx = __float2bfloat16(x - __bfloat162float(hx));
    __nv_bfloat16 ly = __float2bfloat16(y - __bfloat162float(hy));
    hi = packbf(hx, hy);
    lo = packbf(lx, ly);
}
__device__ __forceinline__ void store_split(__nv_bfloat16* ph, __nv_bfloat16* pl,
                                            size_t idx, float v) {
    __nv_bfloat16 h = __float2bfloat16(v);
    ph[idx] = h;
    pl[idx] = __float2bfloat16(v - __bfloat162float(h));
}
__device__ __forceinline__ float warp_sum32(float v) {
#pragma unroll
    for (int o = 16; o > 0; o >>= 1)
        v += __shfl_xor_sync(0xffffffffu, v, o);
    return v;
}

// ---------------------------------------------------------------------------
// fp32 -> bf16 hi/lo conversions
// ---------------------------------------------------------------------------
__global__ void __launch_bounds__(256)
cvt_kernel(const float* __restrict__ src, __nv_bfloat16* __restrict__ hi,
           __nv_bfloat16* __restrict__ lo, int n4)
{
    const int i = blockIdx.x * 256 + threadIdx.x;
    if (i >= n4) return;
    float4 v = ((const float4*)src)[i];
    uint32_t h01, l01, h23, l23;
    split2(v.x, v.y, h01, l01);
    split2(v.z, v.w, h23, l23);
    ((uint2*)hi)[i] = make_uint2(h01, h23);
    ((uint2*)lo)[i] = make_uint2(l01, l23);
}

// all 8 weights in one launch: grid = 8 * 1024 blocks
__global__ void __launch_bounds__(256)
cvt8_kernel(const float* w0, const float* w1, const float* w2, const float* w3,
            const float* w4, const float* w5, const float* w6, const float* w7,
            __nv_bfloat16* __restrict__ hi, __nv_bfloat16* __restrict__ lo)
{
    const int wi = blockIdx.x >> 10;
    const int i  = (blockIdx.x & 1023) * 256 + threadIdx.x;   // float4 idx in weight
    const float* src;
    switch (wi) {
        case 0: src = w0; break;  case 1: src = w1; break;
        case 2: src = w2; break;  case 3: src = w3; break;
        case 4: src = w4; break;  case 5: src = w5; break;
        case 6: src = w6; break;  default: src = w7; break;
    }
    float4 v = ((const float4*)src)[i];
    uint32_t h01, l01, h23, l23;
    split2(v.x, v.y, h01, l01);
    split2(v.z, v.w, h23, l23);
    const size_t o = (size_t)wi * (INNER * INNER / 4) + i;
    ((uint2*)hi)[o] = make_uint2(h01, h23);
    ((uint2*)lo)[o] = make_uint2(l01, l23);
}

// ---------------------------------------------------------------------------
// bf16x3 tensor-core GEMM (NT) with cp.async 2-stage pipeline.
// ---------------------------------------------------------------------------
#define PADK 40
#define GT_TILE  (128 * PADK)
#define GT_STAGE (4 * GT_TILE)
#define GEMM_SMEM_BYTES (2 * GT_STAGE * 2)

__global__ void __launch_bounds__(256, 2)
gemm_bf3_kernel(const __nv_bfloat16* __restrict__ Ah, const __nv_bfloat16* __restrict__ Al,
                const __nv_bfloat16* __restrict__ Wh, const __nv_bfloat16* __restrict__ Wl,
                const float* __restrict__ bias, float* __restrict__ C,
                int M, int N, int K)
{
    extern __shared__ __nv_bfloat16 sm[];
    const int t    = threadIdx.x;
    const int lane = t & 31;
    const int wid  = t >> 5;
    const int wm   = wid >> 1;
    const int wn   = wid & 1;
    const int m0   = blockIdx.y * 128;
    const int n0   = blockIdx.x * 128;

    float acc[2][8][4];
#pragma unroll
    for (int i = 0; i < 2; i++)
#pragma unroll
        for (int j = 0; j < 8; j++)
#pragma unroll
            for (int q = 0; q < 4; q++) acc[i][j][q] = 0.f;

    const int tile = t >> 6;
    const int l64  = t & 63;
    const int lrr  = l64 >> 2;
    const int lcc  = (l64 & 3) * 8;
    const __nv_bfloat16* gsrc =
        (tile == 0) ? Ah : (tile == 1) ? Al : (tile == 2) ? Wh : Wl;
    const int rowbase = (tile < 2) ? m0 : n0;
    const uint32_t smb = smem_u32(sm);
    const uint32_t sdst0 = smb + ((tile * GT_TILE + lrr * PADK + lcc) << 1);
    const __nv_bfloat16* gp = gsrc + (size_t)(rowbase + lrr) * K + lcc;

    const uint32_t abase_rel = (((wm * 32 + (lane & 15)) * PADK + ((lane >> 4) << 3)) << 1);
    const uint32_t bbase_rel = ((2 * GT_TILE +
                     (wn * 64 + (lane & 7) + ((lane >> 4) << 3)) * PADK +
                     (((lane >> 3) & 1) << 3)) << 1);

    const int NT = K / 32;

    {
        const __nv_bfloat16* g = gp;
#pragma unroll
        for (int i = 0; i < 8; i++)
            CP_ASYNC16(sdst0 + (uint32_t)((i * 16 * PADK) << 1),
                       g + (size_t)(i * 16) * K);
        CP_COMMIT();
    }

    for (int kt = 0; kt < NT; kt++) {
        const int b = kt & 1;
        if (kt + 1 < NT) {
            const __nv_bfloat16* g = gp + (kt + 1) * 32;
            const uint32_t d = sdst0 + (uint32_t)((((kt + 1) & 1) * GT_STAGE) << 1);
#pragma unroll
            for (int i = 0; i < 8; i++)
                CP_ASYNC16(d + (uint32_t)((i * 16 * PADK) << 1),
                           g + (size_t)(i * 16) * K);
            CP_COMMIT();
            CP_WAIT1();
        } else {
            CP_WAIT0();
        }
        __syncthreads();

        const uint32_t stage  = smb + (uint32_t)((b * GT_STAGE) << 1);
        const uint32_t abaseh = stage + abase_rel;
        const uint32_t abasel = abaseh + (GT_TILE << 1);
        const uint32_t bbaseh = stage + bbase_rel;
        const uint32_t bbasel = bbaseh + (GT_TILE << 1);

#pragma unroll
        for (int ks = 0; ks < 32; ks += 16) {
            uint32_t a0h[4], a1h[4], a0l[4], a1l[4];
            ldsm_x4(a0h, abaseh + ks * 2);
            ldsm_x4(a1h, abaseh + ks * 2 + 16 * PADK * 2);
            ldsm_x4(a0l, abasel + ks * 2);
            ldsm_x4(a1l, abasel + ks * 2 + 16 * PADK * 2);
#pragma unroll
            for (int nbp = 0; nbp < 4; nbp++) {
                uint32_t bh[4], bl[4];
                ldsm_x4(bh, bbaseh + ks * 2 + nbp * 16 * PADK * 2);
                ldsm_x4(bl, bbasel + ks * 2 + nbp * 16 * PADK * 2);
                // hi*hi
                mma16816(acc[0][2 * nbp],     a0h, bh);
                mma16816(acc[0][2 * nbp + 1], a0h, bh + 2);
                mma16816(acc[1][2 * nbp],     a1h, bh);
                mma16816(acc[1][2 * nbp + 1], a1h, bh + 2);
                // hi*lo
                mma16816(acc[0][2 * nbp],     a0h, bl);
                mma16816(acc[0][2 * nbp + 1], a0h, bl + 2);
                mma16816(acc[1][2 * nbp],     a1h, bl);
                mma16816(acc[1][2 * nbp + 1], a1h, bl + 2);
                // lo*hi
                mma16816(acc[0][2 * nbp],     a0l, bh);
                mma16816(acc[0][2 * nbp + 1], a0l, bh + 2);
                mma16816(acc[1][2 * nbp],     a1l, bh);
                mma16816(acc[1][2 * nbp + 1], a1l, bh + 2);
            }
        }
        __syncthreads();
    }

    const int r0 = m0 + wm * 32 + (lane >> 2);
    const int c0 = n0 + wn * 64 + (lane & 3) * 2;
#pragma unroll
    for (int mi = 0; mi < 2; mi++) {
        const int r = r0 + mi * 16;
#pragma unroll
        for (int nb = 0; nb < 8; nb++) {
            const int c = c0 + nb * 8;
            float b0 = 0.f, b1 = 0.f;
            if (bias) { b0 = bias[c]; b1 = bias[c + 1]; }
            *(float2*)(C + (size_t)r * N + c) =
                make_float2(acc[mi][nb][0] + b0, acc[mi][nb][1] + b1);
            *(float2*)(C + (size_t)(r + 8) * N + c) =
                make_float2(acc[mi][nb][2] + b0, acc[mi][nb][3] + b1);
        }
    }
}

// ---------------------------------------------------------------------------
// RMSNorm + RoPE + sparse scatter (visual)
// ---------------------------------------------------------------------------
__global__ void __launch_bounds__(256)
qkv_post_kernel(const float* __restrict__ qkv,
                const float* __restrict__ gq, const float* __restrict__ gk,
                const float* __restrict__ cosb, const float* __restrict__ sinb,
                __nv_bfloat16* __restrict__ QAh, __nv_bfloat16* __restrict__ QAl,
                __nv_bfloat16* __restrict__ KAh, __nv_bfloat16* __restrict__ KAl,
                __nv_bfloat16* __restrict__ VAh, __nv_bfloat16* __restrict__ VAl)
{
    const int warp = (blockIdx.x * blockDim.x + threadIdx.x) >> 5;
    const int lane = threadIdx.x & 31;
    const int s = warp >> 4;
    const int h = warp & 15;
    if (s >= S_LEN) return;

    const size_t src = (size_t)s * INNER3 + h * HEAD_DIM;
    float q0 = qkv[src + lane],            q1 = qkv[src + lane + 32];
    float k0 = qkv[src + INNER + lane],    k1 = qkv[src + INNER + lane + 32];
    float v0 = qkv[src + 2*INNER + lane],  v1 = qkv[src + 2*INNER + lane + 32];

    float rq = rsqrtf(warp_sum32(q0 * q0 + q1 * q1) * (1.f / HEAD_DIM) + EPS_RMS);
    float rk = rsqrtf(warp_sum32(k0 * k0 + k1 * k1) * (1.f / HEAD_DIM) + EPS_RMS);

    q0 *= rq * gq[lane];  q1 *= rq * gq[lane + 32];
    k0 *= rk * gk[lane];  k1 *= rk * gk[lane + 32];

    const float c0 = cosb[(size_t)s * HEAD_DIM + lane];
    const float c1 = cosb[(size_t)s * HEAD_DIM + lane + 32];
    const float s0 = sinb[(size_t)s * HEAD_DIM + lane];
    const float s1 = sinb[(size_t)s * HEAD_DIM + lane + 32];

    const float oq0 = (q0 * c0 - q1 * s0) * ATTN_SCALE;
    const float oq1 = (q1 * c1 + q0 * s1) * ATTN_SCALE;
    const float ok0 = k0 * c0 - k1 * s0;
    const float ok1 = k1 * c1 + k0 * s1;

    const int j = s & 7, tt = s >> 3;
    const size_t dst = (((size_t)(j * NUM_HEADS + h)) * STOT + tt) * HEAD_DIM;
    store_split(QAh, QAl, dst + lane,      oq0);
    store_split(QAh, QAl, dst + lane + 32, oq1);
    store_split(KAh, KAl, dst + lane,      ok0);
    store_split(KAh, KAl, dst + lane + 32, ok1);
    store_split(VAh, VAl, dst + lane,      v0);
    store_split(VAh, VAl, dst + lane + 32, v1);
}

// ---------------------------------------------------------------------------
// RMSNorm + broadcast scatter (text)
// ---------------------------------------------------------------------------
__global__ void __launch_bounds__(256)
enc_post_kernel(const float* __restrict__ aqkv,
                const float* __restrict__ gaq, const float* __restrict__ gak,
                __nv_bfloat16* __restrict__ QAh, __nv_bfloat16* __restrict__ QAl,
                __nv_bfloat16* __restrict__ KAh, __nv_bfloat16* __restrict__ KAl,
                __nv_bfloat16* __restrict__ VAh, __nv_bfloat16* __restrict__ VAl)
{
    const int warp = (blockIdx.x * blockDim.x + threadIdx.x) >> 5;
    const int lane = threadIdx.x & 31;
    const int tt = warp >> 4;
    const int h  = warp & 15;
    if (tt >= T_LEN) return;

    const size_t src = (size_t)tt * INNER3 + h * HEAD_DIM;
    float a0 = aqkv[src + lane],           a1 = aqkv[src + lane + 32];
    float b0 = aqkv[src + INNER + lane],   b1 = aqkv[src + INNER + lane + 32];
    const float v0 = aqkv[src + 2*INNER + lane], v1 = aqkv[src + 2*INNER + lane + 32];

    float ra = rsqrtf(warp_sum32(a0 * a0 + a1 * a1) * (1.f / HEAD_DIM) + EPS_RMS);
    float rb = rsqrtf(warp_sum32(b0 * b0 + b1 * b1) * (1.f / HEAD_DIM) + EPS_RMS);

    a0 *= ra * gaq[lane] * ATTN_SCALE;  a1 *= ra * gaq[lane + 32] * ATTN_SCALE;
    b0 *= rb * gak[lane];               b1 *= rb * gak[lane + 32];

#pragma unroll
    for (int j = 0; j < SPARSE_N; j++) {
        const size_t dst =
            (((size_t)(j * NUM_HEADS + h)) * STOT + G_LEN + tt) * HEAD_DIM;
        store_split(QAh, QAl, dst + lane,      a0);
        store_split(QAh, QAl, dst + lane + 32, a1);
        store_split(KAh, KAl, dst + lane,      b0);
        store_split(KAh, KAl, dst + lane + 32, b1);
        store_split(VAh, VAl, dst + lane,      v0);
        store_split(VAh, VAl, dst + lane + 32, v1);
    }
}

// ---------------------------------------------------------------------------
// Flash attention, BQ=256, 512 threads (16 warps), cp.async K/V pipeline
// ---------------------------------------------------------------------------
#define APAD 72
#define AQ_ELEMS (2 * 256 * APAD)
#define KV_TILE  (64 * APAD)
#define KV_STAGE (4 * KV_TILE)
#define ATT_SM_BYTES ((AQ_ELEMS + 2 * KV_STAGE) * 2)   // 147456

__global__ void __launch_bounds__(512, 1)
attn_mma_kernel(const __nv_bfloat16* __restrict__ Qhg, const __nv_bfloat16* __restrict__ Qlg,
                const __nv_bfloat16* __restrict__ Khg, const __nv_bfloat16* __restrict__ Klg,
                const __nv_bfloat16* __restrict__ Vhg, const __nv_bfloat16* __restrict__ Vlg,
                float* __restrict__ OA)
{
    extern __shared__ __nv_bfloat16 smA[];
    const int t    = threadIdx.x;
    const int lane = t & 31;
    const int w    = t >> 5;
    const int jh   = blockIdx.y;
    const int q0   = blockIdx.x * 256;
    const size_t base = (size_t)jh * STOT * HEAD_DIM;

    const uint32_t smb = smem_u32(smA);

    // KV loader: tile = t>>7 (0:Kh 1:Kl 2:Vh 3:Vl), 128 threads/tile, 4 chunks
    const int tile = t >> 7;
    const int l128 = t & 127;
    const int krr  = l128 >> 3;          // 0..15
    const int kcc  = (l128 & 7) * 8;
    const __nv_bfloat16* kvsrc =
        (tile == 0) ? Khg : (tile == 1) ? Klg : (tile == 2) ? Vhg : Vlg;
    const uint32_t kvdst0 = smb + ((AQ_ELEMS + tile * KV_TILE + krr * APAD + kcc) << 1);

    {
        const __nv_bfloat16* g = kvsrc + base + (size_t)krr * 64 + kcc;
#pragma unroll
        for (int i = 0; i < 4; i++)
            CP_ASYNC16(kvdst0 + (uint32_t)((i * 16 * APAD) << 1),
                       g + (size_t)(i * 16) * 64);
        CP_COMMIT();
    }

    // Q tile 256x64 hi+lo
    {
        const int row = t >> 1, c0 = (t & 1) * 32;
        const __nv_bfloat16* gh = Qhg + base + (size_t)(q0 + row) * 64 + c0;
        const __nv_bfloat16* gl = Qlg + base + (size_t)(q0 + row) * 64 + c0;
        __nv_bfloat16* sh = smA + row * APAD + c0;
        __nv_bfloat16* sl = smA + 256 * APAD + row * APAD + c0;
#pragma unroll
        for (int c = 0; c < 32; c += 8) {
            *(uint4*)(sh + c) = *(const uint4*)(gh + c);
            *(uint4*)(sl + c) = *(const uint4*)(gl + c);
        }
    }

    float o[8][4];
#pragma unroll
    for (int i = 0; i < 8; i++)
#pragma unroll
        for (int j = 0; j < 4; j++) o[i][j] = 0.f;
    float m0r = -1e30f, m1r = -1e30f, l0r = 0.f, l1r = 0.f;

    const uint32_t qfragh = smb + (((w * 16 + (lane & 15)) * APAD + ((lane >> 4) << 3)) << 1);
    const uint32_t qfragl = qfragh + ((256 * APAD) << 1);
    const uint32_t kfrag_rel = ((((lane & 7) + ((lane >> 4) << 3)) * APAD + (((lane >> 3) & 1) << 3)) << 1);
    const uint32_t vfrag_rel = (((2 * KV_TILE) + ((lane & 7) + (((lane >> 3) & 1) << 3)) * APAD + ((lane >> 4) << 3)) << 1);

    for (int kt = 0; kt < 20; kt++) {
        const int b = kt & 1;
        if (kt + 1 < 20) {
            const __nv_bfloat16* g = kvsrc + base + (size_t)((kt + 1) * 64 + krr) * 64 + kcc;
            const uint32_t d = kvdst0 + (uint32_t)((((kt + 1) & 1) * KV_STAGE) << 1);
#pragma unroll
            for (int i = 0; i < 4; i++)
                CP_ASYNC16(d + (uint32_t)((i * 16 * APAD) << 1),
                           g + (size_t)(i * 16) * 64);
            CP_COMMIT();
            CP_WAIT1();
        } else {
            CP_WAIT0();
        }
        __syncthreads();

        const uint32_t kvstage = smb + (uint32_t)(((AQ_ELEMS + b * KV_STAGE)) << 1);
        const uint32_t kfragh = kvstage + kfrag_rel;
        const uint32_t kfragl = kfragh + (KV_TILE << 1);
        const uint32_t vfrag  = kvstage + vfrag_rel;

        // ---- scores: 3-pass bf16 with fragment reuse ----
        float s[8][4];
#pragma unroll
        for (int i = 0; i < 8; i++)
#pragma unroll
            for (int j = 0; j < 4; j++) s[i][j] = 0.f;

#pragma unroll
        for (int ks = 0; ks < 64; ks += 16) {
            uint32_t ah[4], al[4];
            ldsm_x4(ah, qfragh + ks * 2);
            ldsm_x4(al, qfragl + ks * 2);
#pragma unroll
            for (int nbp = 0; nbp < 4; nbp++) {
                uint32_t kh[4], kl[4];
                ldsm_x4(kh, kfragh + ks * 2 + nbp * 16 * APAD * 2);
                ldsm_x4(kl, kfragl + ks * 2 + nbp * 16 * APAD * 2);
                mma16816(s[2 * nbp],     ah, kh);
                mma16816(s[2 * nbp + 1], ah, kh + 2);
                mma16816(s[2 * nbp],     ah, kl);
                mma16816(s[2 * nbp + 1], ah, kl + 2);
                mma16816(s[2 * nbp],     al, kh);
                mma16816(s[2 * nbp + 1], al, kh + 2);
            }
        }

        // ---- online softmax ----
        float mt0 = -1e30f, mt1 = -1e30f;
#pragma unroll
        for (int nb = 0; nb < 8; nb++) {
            mt0 = fmaxf(mt0, fmaxf(s[nb][0], s[nb][1]));
            mt1 = fmaxf(mt1, fmaxf(s[nb][2], s[nb][3]));
        }
        mt0 = fmaxf(mt0, __shfl_xor_sync(0xffffffffu, mt0, 1));
        mt0 = fmaxf(mt0, __shfl_xor_sync(0xffffffffu, mt0, 2));
        mt1 = fmaxf(mt1, __shfl_xor_sync(0xffffffffu, mt1, 1));
        mt1 = fmaxf(mt1, __shfl_xor_sync(0xffffffffu, mt1, 2));
        const float mn0 = fmaxf(m0r, mt0), mn1 = fmaxf(m1r, mt1);
        const float cf0 = __expf(m0r - mn0), cf1 = __expf(m1r - mn1);
        m0r = mn0;  m1r = mn1;
        float rs0 = 0.f, rs1 = 0.f;
#pragma unroll
        for (int nb = 0; nb < 8; nb++) {
            s[nb][0] = __expf(s[nb][0] - mn0);  rs0 += s[nb][0];
            s[nb][1] = __expf(s[nb][1] - mn0);  rs0 += s[nb][1];
            s[nb][2] = __expf(s[nb][2] - mn1);  rs1 += s[nb][2];
            s[nb][3] = __expf(s[nb][3] - mn1);  rs1 += s[nb][3];
        }
        rs0 += __shfl_xor_sync(0xffffffffu, rs0, 1);
        rs0 += __shfl_xor_sync(0xffffffffu, rs0, 2);
        rs1 += __shfl_xor_sync(0xffffffffu, rs1, 1);
        rs1 += __shfl_xor_sync(0xffffffffu, rs1, 2);
        l0r = l0r * cf0 + rs0;
        l1r = l1r * cf1 + rs1;
#pragma unroll
        for (int db = 0; db < 8; db++) {
            o[db][0] *= cf0;  o[db][1] *= cf0;
            o[db][2] *= cf1;  o[db][3] *= cf1;
        }

        // ---- PV: O += P * V, 3-pass bf16 ----
#pragma unroll
        for (int kb2 = 0; kb2 < 4; kb2++) {
            uint32_t ph[4], pl[4];
            split2(s[2 * kb2][0],     s[2 * kb2][1],     ph[0], pl[0]);
            split2(s[2 * kb2][2],     s[2 * kb2][3],     ph[1], pl[1]);
            split2(s[2 * kb2 + 1][0], s[2 * kb2 + 1][1], ph[2], pl[2]);
            split2(s[2 * kb2 + 1][2], s[2 * kb2 + 1][3], ph[3], pl[3]);
            const uint32_t vb = vfrag + kb2 * 16 * APAD * 2;
#pragma unroll
            for (int dbp = 0; dbp < 4; dbp++) {
                uint32_t vh4[4], vl4[4];
                ldsm_x4_t(vh4, vb + dbp * 16 * 2);
                ldsm_x4_t(vl4, vb + (KV_TILE << 1) + dbp * 16 * 2);
                mma16816(o[2 * dbp],     ph, vh4);
                mma16816(o[2 * dbp + 1], ph, vh4 + 2);
                mma16816(o[2 * dbp],     ph, vl4);
                mma16816(o[2 * dbp + 1], ph, vl4 + 2);
                mma16816(o[2 * dbp],     pl, vh4);
                mma16816(o[2 * dbp + 1], pl, vh4 + 2);
            }
        }
        __syncthreads();
    }

    const float inv0 = 1.f / l0r, inv1 = 1.f / l1r;
    const int row = q0 + w * 16 + (lane >> 2);
    const int col = (lane & 3) * 2;
#pragma unroll
    for (int db = 0; db < 8; db++) {
        *(float2*)(OA + base + (size_t)row * 64 + db * 8 + col) =
            make_float2(o[db][0] * inv0, o[db][1] * inv0);
        *(float2*)(OA + base + (size_t)(row + 8) * 64 + db * 8 + col) =
            make_float2(o[db][2] * inv1, o[db][3] * inv1);
    }
}

// ---------------------------------------------------------------------------
// Gather kernels
// ---------------------------------------------------------------------------
__global__ void __launch_bounds__(256)
gather_vis_kernel(const float* __restrict__ OA,
                  __nv_bfloat16* __restrict__ vh, __nv_bfloat16* __restrict__ vl)
{
    const int i = blockIdx.x * 256 + threadIdx.x;
    const int idx = i * 4;
    const int s = idx >> 10, e = idx & 1023;
    const int j = s & 7, tt = s >> 3;
    const int h = e >> 6, d = e & 63;
    float4 v = *(const float4*)(OA + (((size_t)(j * NUM_HEADS + h)) * STOT + tt) * HEAD_DIM + d);
    uint32_t h01, l01, h23, l23;
    split2(v.x, v.y, h01, l01);
    split2(v.z, v.w, h23, l23);
    ((uint2*)vh)[i] = make_uint2(h01, h23);
    ((uint2*)vl)[i] = make_uint2(l01, l23);
}

__global__ void __launch_bounds__(256)
gather_txt_kernel(const float* __restrict__ OA,
                  __nv_bfloat16* __restrict__ th, __nv_bfloat16* __restrict__ tl)
{
    const int i = blockIdx.x * 256 + threadIdx.x;
    const int idx = i * 4;
    const int tt = idx >> 10, e = idx & 1023;
    const int h = e >> 6, d = e & 63;
    float4 acc = make_float4(0.f, 0.f, 0.f, 0.f);
#pragma unroll
    for (int j = 0; j < SPARSE_N; j++) {
        float4 v = *(const float4*)(OA +
            (((size_t)(j * NUM_HEADS + h)) * STOT + G_LEN + tt) * HEAD_DIM + d);
        acc.x += v.x; acc.y += v.y; acc.z += v.z; acc.w += v.w;
    }
    acc.x *= 0.125f; acc.y *= 0.125f; acc.z *= 0.125f; acc.w *= 0.125f;
    uint32_t h01, l01, h23, l23;
    split2(acc.x, acc.y, h01, l01);
    split2(acc.z, acc.w, h23, l23);
    ((uint2*)th)[i] = make_uint2(h01, h23);
    ((uint2*)tl)[i] = make_uint2(l01, l23);
}

// ---------------------------------------------------------------------------
// kernel_launch
// ---------------------------------------------------------------------------
extern "C" void kernel_launch(void* const* d_in, const int* in_sizes, int n_in,
                              void* d_out, int out_size)
{
    const float* hs   = (const float*)d_in[0];
    const float* enc  = (const float*)d_in[1];
    const float* bout  = (const float*)d_in[9];
    const float* baout = (const float*)d_in[11];
    const float* gq   = (const float*)d_in[12];
    const float* gk   = (const float*)d_in[13];
    const float* gaq  = (const float*)d_in[14];
    const float* gak  = (const float*)d_in[15];
    const float* rc   = (const float*)d_in[16];
    const float* rs   = (const float*)d_in[17];
    float* out = (float*)d_out;

    float *qkvraw, *aqkvraw, *OA;
    __nv_bfloat16 *hs_h, *hs_l, *enc_h, *enc_l, *w_h, *w_l;
    __nv_bfloat16 *vis_h, *vis_l, *txt_h, *txt_l;
    __nv_bfloat16 *QAh, *QAl, *KAh, *KAl, *VAh, *VAl;
    cudaGetSymbolAddress((void**)&qkvraw,  g_qkvraw);
    cudaGetSymbolAddress((void**)&aqkvraw, g_aqkvraw);
    cudaGetSymbolAddress((void**)&OA,    g_OA);
    cudaGetSymbolAddress((void**)&hs_h,  g_hs_h);
    cudaGetSymbolAddress((void**)&hs_l,  g_hs_l);
    cudaGetSymbolAddress((void**)&enc_h, g_enc_h);
    cudaGetSymbolAddress((void**)&enc_l, g_enc_l);
    cudaGetSymbolAddress((void**)&w_h,   g_w_h);
    cudaGetSymbolAddress((void**)&w_l,   g_w_l);
    cudaGetSymbolAddress((void**)&vis_h, g_vis_h);
    cudaGetSymbolAddress((void**)&vis_l, g_vis_l);
    cudaGetSymbolAddress((void**)&txt_h, g_txt_h);
    cudaGetSymbolAddress((void**)&txt_l, g_txt_l);
    cudaGetSymbolAddress((void**)&QAh,   g_QAh);
    cudaGetSymbolAddress((void**)&QAl,   g_QAl);
    cudaGetSymbolAddress((void**)&KAh,   g_KAh);
    cudaGetSymbolAddress((void**)&KAl,   g_KAl);
    cudaGetSymbolAddress((void**)&VAh,   g_VAh);
    cudaGetSymbolAddress((void**)&VAl,   g_VAl);

    cudaFuncSetAttribute(gemm_bf3_kernel,
                         cudaFuncAttributeMaxDynamicSharedMemorySize, GEMM_SMEM_BYTES);
    cudaFuncSetAttribute(attn_mma_kernel,
                         cudaFuncAttributeMaxDynamicSharedMemorySize, ATT_SM_BYTES);

    const size_t WS = (size_t)INNER * INNER;
    dim3 gBig3(INNER3 / 128, S_LEN / 128);   // (24, 64)
    dim3 gEnc3(INNER3 / 128, T_LEN / 128);   // (24, 2)
    dim3 gBig(INNER / 128, S_LEN / 128);
    dim3 gEnc(INNER / 128, T_LEN / 128);

    // [0] all weight conversions in one launch
    cvt8_kernel<<<8 * 1024, 256>>>(
        (const float*)d_in[2], (const float*)d_in[3], (const float*)d_in[4],
        (const float*)d_in[5], (const float*)d_in[6], (const float*)d_in[7],
        (const float*)d_in[8], (const float*)d_in[10], w_h, w_l);
    // [1] hs, [2] enc
    cvt_kernel<<<(S_LEN * INNER / 4) / 256, 256>>>(hs,  hs_h,  hs_l,  S_LEN * INNER / 4);
    cvt_kernel<<<(T_LEN * INNER / 4) / 256, 256>>>(enc, enc_h, enc_l, T_LEN * INNER / 4);

    // [3] encoder merged QKV projection, [4] enc post
    gemm_bf3_kernel<<<gEnc3, 256, GEMM_SMEM_BYTES>>>(
        enc_h, enc_l, w_h + 3 * WS, w_l + 3 * WS, nullptr, aqkvraw, T_LEN, INNER3, INNER);
    enc_post_kernel<<<(T_LEN * NUM_HEADS) / 8, 256>>>(
        aqkvraw, gaq, gak, QAh, QAl, KAh, KAl, VAh, VAl);

    // [5] big merged QKV projection  (ncu -s 5 -c 1 captures this launch)
    gemm_bf3_kernel<<<gBig3, 256, GEMM_SMEM_BYTES>>>(
        hs_h, hs_l, w_h + 0 * WS, w_l + 0 * WS, nullptr, qkvraw, S_LEN, INNER3, INNER);
    // [6] visual post
    qkv_post_kernel<<<(S_LEN * NUM_HEADS) / 8, 256>>>(
        qkvraw, gq, gk, rc, rs, QAh, QAl, KAh, KAl, VAh, VAl);

    // [7] attention (BQ=256)
    attn_mma_kernel<<<dim3(STOT / 256, NJH), 512, ATT_SM_BYTES>>>(
        QAh, QAl, KAh, KAl, VAh, VAl, OA);

    // [8..11] gather + output projections
    gather_vis_kernel<<<(S_LEN * INNER / 4) / 256, 256>>>(OA, vis_h, vis_l);
    gather_txt_kernel<<<(T_LEN * INNER / 4) / 256, 256>>>(OA, txt_h, txt_l);
    gemm_bf3_kernel<<<gBig, 256, GEMM_SMEM_BYTES>>>(
        vis_h, vis_l, w_h + 6 * WS, w_l + 6 * WS, bout, out, S_LEN, INNER, INNER);
    gemm_bf3_kernel<<<gEnc, 256, GEMM_SMEM_BYTES>>>(
        txt_h, txt_l, w_h + 7 * WS, w_l + 7 * WS, baout,
        out + (size_t)S_LEN * INNER, T_LEN, INNER, INNER);
}